// round 11
// baseline (speedup 1.0000x reference)
#include <cuda_runtime.h>
#include <cuda_fp16.h>
#include <cstdint>
#include <math.h>

#define D_MODEL 1024
#define SEQ     2048
#define BATCH   2
#define NHEAD   16
#define DKH     64
#define DFF     4096
#define ROWS    (BATCH*SEQ)   // 4096
#define MEG     (1024*1024)

typedef __half fp16;

// ---------------- scratch (static __device__ arrays; no allocation) ----------------
__device__ float g_bufO[ROWS*D_MODEL];
__device__ float g_bufX1[ROWS*D_MODEL];
__device__ float g_bufX2[ROWS*D_MODEL];
__device__ float g_bias3[3*D_MODEL];
__device__ float g_bias2[2*D_MODEL];

__device__ fp16 g_xh[ROWS*D_MODEL];
__device__ fp16 g_eh[ROWS*D_MODEL];
__device__ fp16 g_wh[16*MEG];
__device__ fp16 g_qkv[ROWS*3*D_MODEL];     // packed Q|K|V (self)
__device__ fp16 g_q2[ROWS*D_MODEL];
__device__ fp16 g_kv2[ROWS*2*D_MODEL];     // packed K|V (cross)
__device__ fp16 g_abh[ROWS*D_MODEL];
__device__ fp16 g_acth[ROWS*D_MODEL];
__device__ fp16 g_hh[ROWS*DFF];

// ---------------- PTX helpers ---------------------------------------------------------
__device__ __forceinline__ uint32_t smem_u32(const void* p) {
    uint32_t a;
    asm("{ .reg .u64 t; cvta.to.shared.u64 t, %1; cvt.u32.u64 %0, t; }" : "=r"(a) : "l"(p));
    return a;
}
#define CP_ASYNC16(dst, src) \
    asm volatile("cp.async.cg.shared.global [%0], [%1], 16;" :: "r"(dst), "l"(src))
#define CP_COMMIT()  asm volatile("cp.async.commit_group;" ::: "memory")
#define CP_WAIT1()   asm volatile("cp.async.wait_group 1;" ::: "memory")
#define CP_WAIT0()   asm volatile("cp.async.wait_group 0;" ::: "memory")

#define LDM_X4(r0, r1, r2, r3, addr) \
    asm volatile("ldmatrix.sync.aligned.m8n8.x4.shared.b16 {%0,%1,%2,%3}, [%4];" \
        : "=r"(r0), "=r"(r1), "=r"(r2), "=r"(r3) : "r"(addr))
#define LDM_X4T(r0, r1, r2, r3, addr) \
    asm volatile("ldmatrix.sync.aligned.m8n8.x4.trans.shared.b16 {%0,%1,%2,%3}, [%4];" \
        : "=r"(r0), "=r"(r1), "=r"(r2), "=r"(r3) : "r"(addr))

#define MMA_F16(c, a, b0, b1) \
    asm volatile("mma.sync.aligned.m16n8k16.row.col.f32.f16.f16.f32 " \
        "{%0,%1,%2,%3}, {%4,%5,%6,%7}, {%8,%9}, {%0,%1,%2,%3};" \
        : "+f"((c)[0]), "+f"((c)[1]), "+f"((c)[2]), "+f"((c)[3]) \
        : "r"((a)[0]), "r"((a)[1]), "r"((a)[2]), "r"((a)[3]), "r"(b0), "r"(b1))

__device__ __forceinline__ uint32_t pack_h2(float lo, float hi) {
    __half2 t; t.x = __float2half_rn(lo); t.y = __float2half_rn(hi);
    return *(uint32_t*)&t;
}

// ---------------- tensor-core GEMM: C[M,N] = A B^T + bias ----------------------------
// 256x128 CTA tile, 8 warps as 4x2 of 64x64 warp tiles, KC=64, 3-stage cp.async ring.
// Columns [0, scaleN) get multiplied by oscale after bias (+relu).
#define GKC      64
#define GLDS_EL  72                 // 64 + 8 pad fp16 per smem row
#define GLDS_B   (GLDS_EL*2)        // 144 B
#define GTILE_A  (256*GLDS_B)       // 36864 B (A: 256 rows)
#define GTILE_Bt (128*GLDS_B)       // 18432 B (B: 128 rows)
#define GBUF_B   (GTILE_A+GTILE_Bt) // 55296 B per stage
#define GSTAGES  3
#define GEMM_SMEM (GSTAGES*GBUF_B)  // 165888 B

__global__ __launch_bounds__(256)
void gemm_tc(const fp16* __restrict__ A, const fp16* __restrict__ B,
             const float* __restrict__ bias, float* __restrict__ C,
             fp16* __restrict__ Ch,
             int M, int N, int K, int relu, float oscale, int scaleN)
{
    extern __shared__ char smem[];
    const uint32_t sb = smem_u32(smem);
    const int tid  = threadIdx.x;
    const int wid  = tid >> 5, lane = tid & 31;
    const int rowBase = blockIdx.y * 256;
    const int colBase = blockIdx.x * 128;
    const int warpRow = (wid & 3) * 64;        // 4 warp-rows
    const int warpCol = (wid >> 2) * 64;       // 2 warp-cols

    const int nch = K / GKC;

    const int aRowL = (lane & 7) + ((lane >> 3) & 1) * 8;
    const int aColL = (lane >> 4) * 8;
    const int bRowL = (lane & 7) + (lane >> 4) * 8;
    const int bColL = ((lane >> 3) & 1) * 8;

    float acc[4][8][4];
#pragma unroll
    for (int mt = 0; mt < 4; mt++)
#pragma unroll
        for (int nt = 0; nt < 8; nt++)
#pragma unroll
            for (int r = 0; r < 4; r++) acc[mt][nt][r] = 0.f;

    // ---- chunk issue: A 256 rows (8/thread) + B 128 rows (4/thread) ----
    auto issue_chunk = [&](int chunk, int stage) {
        const uint32_t dbase = sb + stage * GBUF_B;
        const int gk = chunk * GKC;
#pragma unroll
        for (int i = 0; i < 8; i++) {
            const int within = i * 256 + tid;            // 0..2047
            const int r = within >> 3, seg = within & 7;
            const fp16* gp = A + (size_t)(rowBase + r) * K + gk + seg * 8;
            CP_ASYNC16(dbase + r * GLDS_B + seg * 16, gp);
        }
#pragma unroll
        for (int i = 0; i < 4; i++) {
            const int within = i * 256 + tid;            // 0..1023
            const int r = within >> 3, seg = within & 7;
            const fp16* gp = B + (size_t)(colBase + r) * K + gk + seg * 8;
            CP_ASYNC16(dbase + GTILE_A + r * GLDS_B + seg * 16, gp);
        }
        CP_COMMIT();
    };

    // ---- prologue: stages 0,1 in flight ----
    issue_chunk(0, 0);
    issue_chunk(1, 1);

    for (int kc = 0; kc < nch; kc++) {
        if (kc + 1 < nch) { CP_WAIT1(); } else { CP_WAIT0(); }
        __syncthreads();

        const uint32_t cb = sb + (kc % GSTAGES) * GBUF_B;
        const uint32_t As = cb, Bs = cb + GTILE_A;

#pragma unroll
        for (int ks = 0; ks < 4; ks++) {
            const int kcol = ks * 16;
            uint32_t af[4][4], bf[4][4];
#pragma unroll
            for (int mt = 0; mt < 4; mt++) {
                const uint32_t off = (uint32_t)(warpRow + mt * 16 + aRowL) * GLDS_B
                                   + (uint32_t)(kcol + aColL) * 2;
                LDM_X4(af[mt][0], af[mt][1], af[mt][2], af[mt][3], As + off);
            }
#pragma unroll
            for (int np = 0; np < 4; np++) {
                const uint32_t off = (uint32_t)(warpCol + np * 16 + bRowL) * GLDS_B
                                   + (uint32_t)(kcol + bColL) * 2;
                LDM_X4(bf[np][0], bf[np][1], bf[np][2], bf[np][3], Bs + off);
            }
#pragma unroll
            for (int mt = 0; mt < 4; mt++)
#pragma unroll
                for (int nt = 0; nt < 8; nt++) {
                    const int ntp = nt >> 1, q = (nt & 1) * 2;
                    MMA_F16(acc[mt][nt], af[mt], bf[ntp][q], bf[ntp][q + 1]);
                }
        }

        if (kc + 2 < nch) issue_chunk(kc + 2, (kc + 2) % GSTAGES);
    }

    const int lr = lane >> 2, lc = (lane & 3) * 2;
#pragma unroll
    for (int mt = 0; mt < 4; mt++) {
#pragma unroll
        for (int nt = 0; nt < 8; nt++) {
            const int col = colBase + warpCol + nt * 8 + lc;
            const float sc = (col < scaleN) ? oscale : 1.0f;
            const float b0 = __ldg(&bias[col]);
            const float b1 = __ldg(&bias[col + 1]);
#pragma unroll
            for (int h = 0; h < 2; h++) {
                const int row = rowBase + warpRow + mt * 16 + lr + h * 8;
                float v0 = acc[mt][nt][2 * h]     + b0;
                float v1 = acc[mt][nt][2 * h + 1] + b1;
                if (relu) { v0 = fmaxf(v0, 0.f); v1 = fmaxf(v1, 0.f); }
                v0 *= sc; v1 *= sc;
                const size_t off = (size_t)row * N + col;
                if (C) *(float2*)(C + off) = make_float2(v0, v1);
                if (Ch) {
                    __half2 hh; hh.x = __float2half_rn(v0); hh.y = __float2half_rn(v1);
                    *(__half2*)(Ch + off) = hh;
                }
            }
        }
    }
}

// ---------------- tensor-core flash attention -----------------------------------------
// 128 q-rows/CTA, 64-key tiles, 8 warps x 16 rows. Strided Q/KV (packed projections).
#define FA_STR  72
#define FA_RB   (FA_STR*2)             // 144 B
#define FA_KVT  (64*FA_RB)             // 9216 B
#define FA_BUF  (2*FA_KVT)             // K,V
#define FA_SMEM (2*FA_BUF)             // 36864 B

template<bool CAUSAL>
__global__ __launch_bounds__(256)
void flash_tc(const fp16* __restrict__ Qh, const fp16* __restrict__ Kh,
              const fp16* __restrict__ Vh, fp16* __restrict__ Oh,
              int SK, int qstr, int kstr)
{
    extern __shared__ char smem[];
    const uint32_t sb = smem_u32(smem);
    const int tid = threadIdx.x;
    const int wid = tid >> 5, lane = tid & 31;
    const int b = blockIdx.z, h = blockIdx.y, qt = blockIdx.x;
    const int qbase = qt * 128;

    const size_t qoff = ((size_t)b * SEQ + qbase) * qstr + h * DKH;
    const size_t koff = (size_t)b * SK * kstr + h * DKH;

    // stage Q, build fragments, release smem
    {
        const fp16* qp = Qh + qoff;
#pragma unroll
        for (int i = 0; i < 4; i++) {
            const int idx = i * 256 + tid;
            const int r = idx >> 3, seg = idx & 7;
            CP_ASYNC16(sb + r * FA_RB + seg * 16, qp + (size_t)r * qstr + seg * 8);
        }
        CP_COMMIT();
        CP_WAIT0();
        __syncthreads();
    }

    const int aRowL = (lane & 7) + ((lane >> 3) & 1) * 8;
    const int aColL = (lane >> 4) * 8;
    uint32_t qf[4][4];
#pragma unroll
    for (int ks = 0; ks < 4; ks++) {
        const uint32_t off = (uint32_t)(wid * 16 + aRowL) * FA_RB + (uint32_t)(ks * 16 + aColL) * 2;
        LDM_X4(qf[ks][0], qf[ks][1], qf[ks][2], qf[ks][3], sb + off);
    }
    __syncthreads();

    float o[8][4];
#pragma unroll
    for (int dt = 0; dt < 8; dt++)
#pragma unroll
        for (int r = 0; r < 4; r++) o[dt][r] = 0.f;
    float m0 = -1e30f, m1 = -1e30f, l0 = 0.f, l1 = 0.f;

    const int r0g = qbase + wid * 16 + (lane >> 2);
    const int r1g = r0g + 8;
    const int nkt = CAUSAL ? (qt * 2 + 2) : (SK >> 6);

    // prologue: tile 0 -> buf 0
    {
#pragma unroll
        for (int i = 0; i < 2; i++) {
            const int idx = i * 256 + tid;
            const int r = idx >> 3, seg = idx & 7;
            const size_t g = koff + (size_t)r * kstr + seg * 8;
            CP_ASYNC16(sb + 0 * FA_KVT + r * FA_RB + seg * 16, Kh + g);
            CP_ASYNC16(sb + 1 * FA_KVT + r * FA_RB + seg * 16, Vh + g);
        }
        CP_COMMIT();
    }

    const int bRowL = (lane & 7) + (lane >> 4) * 8;
    const int bColL = ((lane >> 3) & 1) * 8;
    const int vRowL = lane & 15;
    const int vColL = (lane >> 4) * 8;

    for (int kt = 0; kt < nkt; kt++) {
        if (kt + 1 < nkt) {
            const uint32_t db = sb + ((kt + 1) & 1) * FA_BUF;
            const size_t kb = koff + (size_t)(kt + 1) * 64 * kstr;
#pragma unroll
            for (int i = 0; i < 2; i++) {
                const int idx = i * 256 + tid;
                const int r = idx >> 3, seg = idx & 7;
                const size_t g = kb + (size_t)r * kstr + seg * 8;
                CP_ASYNC16(db + 0 * FA_KVT + r * FA_RB + seg * 16, Kh + g);
                CP_ASYNC16(db + 1 * FA_KVT + r * FA_RB + seg * 16, Vh + g);
            }
            CP_COMMIT();
            CP_WAIT1();
        } else {
            CP_WAIT0();
        }
        __syncthreads();

        const uint32_t cb = sb + (kt & 1) * FA_BUF;
        const uint32_t Khs = cb, Vhs = cb + FA_KVT;

        // ---- S = Q K^T (exp2 domain, scale folded into Q) ----
        float s[8][4];
#pragma unroll
        for (int nt = 0; nt < 8; nt++)
#pragma unroll
            for (int r = 0; r < 4; r++) s[nt][r] = 0.f;

#pragma unroll
        for (int ks = 0; ks < 4; ks++) {
#pragma unroll
            for (int np = 0; np < 4; np++) {
                uint32_t kf[4];
                const uint32_t off = (uint32_t)(np * 16 + bRowL) * FA_RB
                                   + (uint32_t)(ks * 16 + bColL) * 2;
                LDM_X4(kf[0], kf[1], kf[2], kf[3], Khs + off);
#pragma unroll
                for (int hf = 0; hf < 2; hf++) {
                    const int nt = np * 2 + hf, q = hf * 2;
                    MMA_F16(s[nt], qf[ks], kf[q], kf[q + 1]);
                }
            }
        }

        if (CAUSAL) {
            const int kb = kt * 64;
            if (kb + 63 > r0g) {
#pragma unroll
                for (int nt = 0; nt < 8; nt++)
#pragma unroll
                    for (int c = 0; c < 2; c++) {
                        const int key = kb + nt * 8 + ((lane & 3) << 1) + c;
                        if (key > r0g) s[nt][c]     = -1e30f;
                        if (key > r1g) s[nt][2 + c] = -1e30f;
                    }
            }
        }

        // ---- online softmax (base-2) ----
        float mx0 = -1e30f, mx1 = -1e30f;
#pragma unroll
        for (int nt = 0; nt < 8; nt++) {
            mx0 = fmaxf(mx0, fmaxf(s[nt][0], s[nt][1]));
            mx1 = fmaxf(mx1, fmaxf(s[nt][2], s[nt][3]));
        }
        mx0 = fmaxf(mx0, __shfl_xor_sync(0xffffffffu, mx0, 1, 4));
        mx0 = fmaxf(mx0, __shfl_xor_sync(0xffffffffu, mx0, 2, 4));
        mx1 = fmaxf(mx1, __shfl_xor_sync(0xffffffffu, mx1, 1, 4));
        mx1 = fmaxf(mx1, __shfl_xor_sync(0xffffffffu, mx1, 2, 4));
        const float mn0 = fmaxf(m0, mx0), mn1 = fmaxf(m1, mx1);
        const float c0 = exp2f(m0 - mn0), c1 = exp2f(m1 - mn1);
        float rs0 = 0.f, rs1 = 0.f;
#pragma unroll
        for (int nt = 0; nt < 8; nt++) {
            s[nt][0] = exp2f(s[nt][0] - mn0);
            s[nt][1] = exp2f(s[nt][1] - mn0);
            s[nt][2] = exp2f(s[nt][2] - mn1);
            s[nt][3] = exp2f(s[nt][3] - mn1);
            rs0 += s[nt][0] + s[nt][1];
            rs1 += s[nt][2] + s[nt][3];
        }
        rs0 += __shfl_xor_sync(0xffffffffu, rs0, 1, 4);
        rs0 += __shfl_xor_sync(0xffffffffu, rs0, 2, 4);
        rs1 += __shfl_xor_sync(0xffffffffu, rs1, 1, 4);
        rs1 += __shfl_xor_sync(0xffffffffu, rs1, 2, 4);
        l0 = l0 * c0 + rs0; l1 = l1 * c1 + rs1;
        m0 = mn0; m1 = mn1;
#pragma unroll
        for (int dt = 0; dt < 8; dt++) {
            o[dt][0] *= c0; o[dt][1] *= c0;
            o[dt][2] *= c1; o[dt][3] *= c1;
        }

        // ---- O += P V ----
#pragma unroll
        for (int ks = 0; ks < 4; ks++) {
            const int nt0 = 2 * ks, nt1 = 2 * ks + 1;
            uint32_t pf[4];
            pf[0] = pack_h2(s[nt0][0], s[nt0][1]);
            pf[1] = pack_h2(s[nt0][2], s[nt0][3]);
            pf[2] = pack_h2(s[nt1][0], s[nt1][1]);
            pf[3] = pack_h2(s[nt1][2], s[nt1][3]);
#pragma unroll
            for (int dp = 0; dp < 4; dp++) {
                uint32_t vf[4];
                const uint32_t off = (uint32_t)(ks * 16 + vRowL) * FA_RB
                                   + (uint32_t)(dp * 16 + vColL) * 2;
                LDM_X4T(vf[0], vf[1], vf[2], vf[3], Vhs + off);
#pragma unroll
                for (int hf = 0; hf < 2; hf++) {
                    const int dt = dp * 2 + hf, q = hf * 2;
                    MMA_F16(o[dt], pf, vf[q], vf[q + 1]);
                }
            }
        }
        __syncthreads();
    }

    // ---- epilogue: O /= l, write fp16 ----
    const float i0 = 1.f / l0, i1 = 1.f / l1;
    const int dcol = h * DKH + (lane & 3) * 2;
    const size_t ro0 = ((size_t)b * SEQ + r0g) * D_MODEL;
    const size_t ro1 = ((size_t)b * SEQ + r1g) * D_MODEL;
#pragma unroll
    for (int dt = 0; dt < 8; dt++) {
        const int dc = dcol + dt * 8;
        __half2 hh0; hh0.x = __float2half_rn(o[dt][0] * i0); hh0.y = __float2half_rn(o[dt][1] * i0);
        __half2 hh1; hh1.x = __float2half_rn(o[dt][2] * i1); hh1.y = __float2half_rn(o[dt][3] * i1);
        *(__half2*)(Oh + ro0 + dc) = hh0;
        *(__half2*)(Oh + ro1 + dc) = hh1;
    }
}

// ---------------- fused residual-add + LayerNorm (+ fp16 out) ------------------------
__global__ __launch_bounds__(256)
void add_ln_kernel(const float* __restrict__ X, const float* __restrict__ R,
                   const float* __restrict__ gamma, const float* __restrict__ beta,
                   float* __restrict__ Y, fp16* __restrict__ Yh)
{
    const int row = blockIdx.x;
    const int t = threadIdx.x;
    const float4 xv = ((const float4*)(X + (size_t)row * D_MODEL))[t];
    const float4 rv = ((const float4*)(R + (size_t)row * D_MODEL))[t];
    float v0 = xv.x + rv.x, v1 = xv.y + rv.y, v2 = xv.z + rv.z, v3 = xv.w + rv.w;

    float s  = v0 + v1 + v2 + v3;
    float ss = v0 * v0 + v1 * v1 + v2 * v2 + v3 * v3;
#pragma unroll
    for (int o = 16; o > 0; o >>= 1) {
        s  += __shfl_xor_sync(0xffffffffu, s,  o);
        ss += __shfl_xor_sync(0xffffffffu, ss, o);
    }
    __shared__ float sbuf[8], ssbuf[8];
    int w = t >> 5, ln = t & 31;
    if (ln == 0) { sbuf[w] = s; ssbuf[w] = ss; }
    __syncthreads();
    s = 0.f; ss = 0.f;
#pragma unroll
    for (int i = 0; i < 8; i++) { s += sbuf[i]; ss += ssbuf[i]; }

    const float mu  = s * (1.f / 1024.f);
    const float var = ss * (1.f / 1024.f) - mu * mu;
    const float rs  = rsqrtf(var + 1e-5f);
    const float4 gv = ((const float4*)gamma)[t];
    const float4 bv = ((const float4*)beta)[t];
    float4 o;
    o.x = (v0 - mu) * rs * gv.x + bv.x;
    o.y = (v1 - mu) * rs * gv.y + bv.y;
    o.z = (v2 - mu) * rs * gv.z + bv.z;
    o.w = (v3 - mu) * rs * gv.w + bv.w;
    ((float4*)(Y + (size_t)row * D_MODEL))[t] = o;

    if (Yh) {
        size_t off = (size_t)row * D_MODEL + t * 4;
        __half2 hh0; hh0.x = __float2half_rn(o.x); hh0.y = __float2half_rn(o.y);
        __half2 hh1; hh1.x = __float2half_rn(o.z); hh1.y = __float2half_rn(o.w);
        *(__half2*)(Yh + off)     = hh0;
        *(__half2*)(Yh + off + 2) = hh1;
    }
}

// ---------------- fp32 -> fp16 converts -----------------------------------------------
__global__ __launch_bounds__(256)
void cvt_kernel(const float4* __restrict__ src, __half2* __restrict__ dst, int n4)
{
    int i = blockIdx.x * blockDim.x + threadIdx.x;
    if (i >= n4) return;
    float4 v = src[i];
    __half2 a; a.x = __float2half_rn(v.x); a.y = __float2half_rn(v.y);
    __half2 b; b.x = __float2half_rn(v.z); b.y = __float2half_rn(v.w);
    dst[2 * i] = a; dst[2 * i + 1] = b;
}

// converts ALL weight matrices into the packed g_wh in one launch.
// layout (elements): [0..8M) = 8 x 1M mats, [8M..12M) = Wf1, [12M..16M) = Wf2.
// Launched with 4*MEG threads (one per float4 of the 16M-element total).
__global__ __launch_bounds__(256)
void cvt_w_kernel(const float4* w0, const float4* w1, const float4* w2, const float4* w3,
                  const float4* w4, const float4* w5, const float4* w6, const float4* w7,
                  const float4* wf1, const float4* wf2, __half2* __restrict__ dst)
{
    const int i = blockIdx.x * blockDim.x + threadIdx.x;       // 0 .. 4M-1 float4s
    const int S = MEG / 4;                                     // 262144 float4 per MEG
    const int slot = i >> 18;
    const float4* src; int off;
    switch (slot) {
        case 0: src = w0; off = i;         break;
        case 1: src = w1; off = i - S;     break;
        case 2: src = w2; off = i - 2*S;   break;
        case 3: src = w3; off = i - 3*S;   break;
        case 4: src = w4; off = i - 4*S;   break;
        case 5: src = w5; off = i - 5*S;   break;
        case 6: src = w6; off = i - 6*S;   break;
        case 7: src = w7; off = i - 7*S;   break;
        case 8: case 9: case 10: case 11:
                src = wf1; off = i - 8*S;  break;
        default:
                src = wf2; off = i - 12*S; break;
    }
    float4 v = src[off];
    __half2 a; a.x = __float2half_rn(v.x); a.y = __float2half_rn(v.y);
    __half2 b; b.x = __float2half_rn(v.z); b.y = __float2half_rn(v.w);
    dst[2 * i] = a; dst[2 * i + 1] = b;
}

// ---------------- orchestration -------------------------------------------------------
static inline void gemm(const fp16* A, const fp16* B, const float* bias,
                        float* C, fp16* Ch, int M, int N, int K, int relu,
                        float oscale = 1.0f, int scaleN = 0)
{
    dim3 g(N / 128, M / 256);
    gemm_tc<<<g, 256, GEMM_SMEM>>>(A, B, bias, C, Ch, M, N, K, relu, oscale, scaleN);
}

static inline void cvt(const float* src, fp16* dst, int n)
{
    int n4 = n / 4;
    cvt_kernel<<<(n4 + 255) / 256, 256>>>((const float4*)src, (__half2*)dst, n4);
}

extern "C" void kernel_launch(void* const* d_in, const int* in_sizes, int n_in,
                              void* d_out, int out_size)
{
    const float* x   = (const float*)d_in[0];
    const float* enc = (const float*)d_in[1];
    const float* Wq1 = (const float*)d_in[4],  *bq1 = (const float*)d_in[5];
    const float* Wk1 = (const float*)d_in[6],  *bk1 = (const float*)d_in[7];
    const float* Wv1 = (const float*)d_in[8],  *bv1 = (const float*)d_in[9];
    const float* Wo1 = (const float*)d_in[10], *bo1 = (const float*)d_in[11];
    const float* Wq2 = (const float*)d_in[12], *bq2 = (const float*)d_in[13];
    const float* Wk2 = (const float*)d_in[14], *bk2 = (const float*)d_in[15];
    const float* Wv2 = (const float*)d_in[16], *bv2 = (const float*)d_in[17];
    const float* Wo2 = (const float*)d_in[18], *bo2 = (const float*)d_in[19];
    const float* Wf1 = (const float*)d_in[20], *bf1 = (const float*)d_in[21];
    const float* Wf2 = (const float*)d_in[22], *bf2 = (const float*)d_in[23];
    const float* g1  = (const float*)d_in[24], *be1 = (const float*)d_in[25];
    const float* g2  = (const float*)d_in[26], *be2 = (const float*)d_in[27];
    const float* g3  = (const float*)d_in[28], *be3 = (const float*)d_in[29];
    float* out = (float*)d_out;

    const float QSCALE = 0.125f * 1.4426950408889634f;

    cudaFuncSetAttribute(gemm_tc, cudaFuncAttributeMaxDynamicSharedMemorySize, GEMM_SMEM);
    cudaFuncSetAttribute(flash_tc<true>,  cudaFuncAttributeMaxDynamicSharedMemorySize, FA_SMEM);
    cudaFuncSetAttribute(flash_tc<false>, cudaFuncAttributeMaxDynamicSharedMemorySize, FA_SMEM);

    float *Ob, *X1, *X2, *bias3, *bias2;
    cudaGetSymbolAddress((void**)&Ob, g_bufO);
    cudaGetSymbolAddress((void**)&X1, g_bufX1);
    cudaGetSymbolAddress((void**)&X2, g_bufX2);
    cudaGetSymbolAddress((void**)&bias3, g_bias3);
    cudaGetSymbolAddress((void**)&bias2, g_bias2);
    fp16 *xh, *eh, *wh, *qkv, *q2, *kv2, *abh, *acth, *hh;
    cudaGetSymbolAddress((void**)&xh,   g_xh);
    cudaGetSymbolAddress((void**)&eh,   g_eh);
    cudaGetSymbolAddress((void**)&wh,   g_wh);
    cudaGetSymbolAddress((void**)&qkv,  g_qkv);
    cudaGetSymbolAddress((void**)&q2,   g_q2);
    cudaGetSymbolAddress((void**)&kv2,  g_kv2);
    cudaGetSymbolAddress((void**)&abh,  g_abh);
    cudaGetSymbolAddress((void**)&acth, g_acth);
    cudaGetSymbolAddress((void**)&hh,   g_hh);

    // packed weight slots (elements): QKV1 at 0, O1 at 3M, Q2 at 4M, KV2 at 5M, O2 at 7M
    const size_t OQKV1 = 0, OO1 = 3 * MEG, OQ2 = 4 * MEG, OKV2 = 5 * MEG, OO2 = 7 * MEG;
    const size_t OF1 = 8 * MEG, OF2 = 12 * MEG;

    // converts: 16M weight elements = 4M float4s -> 4M threads
    cvt_w_kernel<<<(4 * MEG) / 256, 256>>>(
        (const float4*)Wq1, (const float4*)Wk1, (const float4*)Wv1, (const float4*)Wo1,
        (const float4*)Wq2, (const float4*)Wk2, (const float4*)Wv2, (const float4*)Wo2,
        (const float4*)Wf1, (const float4*)Wf2, (__half2*)wh);
    cvt(x,   xh, ROWS * D_MODEL);
    cvt(enc, eh, ROWS * D_MODEL);

    // packed bias vectors
    cudaMemcpyAsync(bias3,              bq1, D_MODEL * 4, cudaMemcpyDeviceToDevice);
    cudaMemcpyAsync(bias3 + D_MODEL,    bk1, D_MODEL * 4, cudaMemcpyDeviceToDevice);
    cudaMemcpyAsync(bias3 + 2*D_MODEL,  bv1, D_MODEL * 4, cudaMemcpyDeviceToDevice);
    cudaMemcpyAsync(bias2,              bk2, D_MODEL * 4, cudaMemcpyDeviceToDevice);
    cudaMemcpyAsync(bias2 + D_MODEL,    bv2, D_MODEL * 4, cudaMemcpyDeviceToDevice);

    dim3 gf(SEQ / 128, NHEAD, BATCH);

    // ---- self-attention (causal): fused QKV projection, N=3072 ----
    gemm(xh, wh + OQKV1, bias3, 0, qkv, ROWS, 3 * D_MODEL, D_MODEL, 0, QSCALE, D_MODEL);
    flash_tc<true><<<gf, 256, FA_SMEM>>>(qkv, qkv + D_MODEL, qkv + 2 * D_MODEL, abh,
                                         SEQ, 3 * D_MODEL, 3 * D_MODEL);
    gemm(abh, wh + OO1, bo1, Ob, 0, ROWS, D_MODEL, D_MODEL, 0);
    add_ln_kernel<<<ROWS, 256>>>(x, Ob, g1, be1, X1, acth);

    // ---- cross-attention (unmasked): fused KV projection, N=2048 ----
    gemm(acth, wh + OQ2, bq2, 0, q2, ROWS, D_MODEL, D_MODEL, 0, QSCALE, D_MODEL);
    gemm(eh, wh + OKV2, bias2, 0, kv2, ROWS, 2 * D_MODEL, D_MODEL, 0);
    flash_tc<false><<<gf, 256, FA_SMEM>>>(q2, kv2, kv2 + D_MODEL, abh,
                                          SEQ, D_MODEL, 2 * D_MODEL);
    gemm(abh, wh + OO2, bo2, Ob, 0, ROWS, D_MODEL, D_MODEL, 0);
    add_ln_kernel<<<ROWS, 256>>>(X1, Ob, g2, be2, X2, acth);

    // ---- FFN ----
    gemm(acth, wh + OF1, bf1, 0, hh, ROWS, DFF, D_MODEL, 1);
    gemm(hh, wh + OF2, bf2, Ob, 0, ROWS, D_MODEL, DFF, 0);
    add_ln_kernel<<<ROWS, 256>>>(X2, Ob, g3, be3, out, 0);
}

// round 12
// speedup vs baseline: 1.0819x; 1.0819x over previous
#include <cuda_runtime.h>
#include <cuda_fp16.h>
#include <cstdint>
#include <math.h>

#define D_MODEL 1024
#define SEQ     2048
#define BATCH   2
#define NHEAD   16
#define DKH     64
#define DFF     4096
#define ROWS    (BATCH*SEQ)   // 4096
#define MEG     (1024*1024)

typedef __half fp16;

// ---------------- scratch (static __device__ arrays; no allocation) ----------------
__device__ float g_bufO[ROWS*D_MODEL];
__device__ float g_bufX1[ROWS*D_MODEL];
__device__ float g_bufX2[ROWS*D_MODEL];
__device__ float g_bias3[3*D_MODEL];
__device__ float g_bias2[2*D_MODEL];

__device__ fp16 g_xh[ROWS*D_MODEL];
__device__ fp16 g_eh[ROWS*D_MODEL];
__device__ fp16 g_wh[16*MEG];
__device__ fp16 g_qkv[ROWS*3*D_MODEL];     // packed Q|K|V (self)
__device__ fp16 g_q2[ROWS*D_MODEL];
__device__ fp16 g_kv2[ROWS*2*D_MODEL];     // packed K|V (cross)
__device__ fp16 g_abh[ROWS*D_MODEL];
__device__ fp16 g_acth[ROWS*D_MODEL];
__device__ fp16 g_hh[ROWS*DFF];

// ---------------- PTX helpers ---------------------------------------------------------
__device__ __forceinline__ uint32_t smem_u32(const void* p) {
    uint32_t a;
    asm("{ .reg .u64 t; cvta.to.shared.u64 t, %1; cvt.u32.u64 %0, t; }" : "=r"(a) : "l"(p));
    return a;
}
#define CP_ASYNC16(dst, src) \
    asm volatile("cp.async.cg.shared.global [%0], [%1], 16;" :: "r"(dst), "l"(src))
#define CP_COMMIT()  asm volatile("cp.async.commit_group;" ::: "memory")
#define CP_WAIT1()   asm volatile("cp.async.wait_group 1;" ::: "memory")
#define CP_WAIT0()   asm volatile("cp.async.wait_group 0;" ::: "memory")

#define LDM_X4(r0, r1, r2, r3, addr) \
    asm volatile("ldmatrix.sync.aligned.m8n8.x4.shared.b16 {%0,%1,%2,%3}, [%4];" \
        : "=r"(r0), "=r"(r1), "=r"(r2), "=r"(r3) : "r"(addr))
#define LDM_X4T(r0, r1, r2, r3, addr) \
    asm volatile("ldmatrix.sync.aligned.m8n8.x4.trans.shared.b16 {%0,%1,%2,%3}, [%4];" \
        : "=r"(r0), "=r"(r1), "=r"(r2), "=r"(r3) : "r"(addr))

#define MMA_F16(c, a, b0, b1) \
    asm volatile("mma.sync.aligned.m16n8k16.row.col.f32.f16.f16.f32 " \
        "{%0,%1,%2,%3}, {%4,%5,%6,%7}, {%8,%9}, {%0,%1,%2,%3};" \
        : "+f"((c)[0]), "+f"((c)[1]), "+f"((c)[2]), "+f"((c)[3]) \
        : "r"((a)[0]), "r"((a)[1]), "r"((a)[2]), "r"((a)[3]), "r"(b0), "r"(b1))

__device__ __forceinline__ uint32_t pack_h2(float lo, float hi) {
    __half2 t; t.x = __float2half_rn(lo); t.y = __float2half_rn(hi);
    return *(uint32_t*)&t;
}

// ---------------- tensor-core GEMM: C[M,N] = A B^T + bias ----------------------------
// 128x128 CTA tile, 8 warps (64x32), KC=64, 3-stage cp.async ring, one sync per chunk.
// (round-9 configuration — best measured)
#define GKC      64
#define GLDS_EL  72                 // 64 + 8 pad fp16 per smem row
#define GLDS_B   (GLDS_EL*2)        // 144 B
#define GTILE_B  (128*GLDS_B)       // 18432 B per operand tile
#define GBUF_B   (2*GTILE_B)        // 36864 B per stage (A+B)
#define GSTAGES  3
#define GEMM_SMEM (GSTAGES*GBUF_B)  // 110592 B

__global__ __launch_bounds__(256)
void gemm_tc(const fp16* __restrict__ A, const fp16* __restrict__ B,
             const float* __restrict__ bias, float* __restrict__ C,
             fp16* __restrict__ Ch,
             int M, int N, int K, int relu, float oscale, int scaleN)
{
    extern __shared__ char smem[];
    const uint32_t sb = smem_u32(smem);
    const int tid  = threadIdx.x;
    const int wid  = tid >> 5, lane = tid & 31;
    const int rowBase = blockIdx.y * 128;
    const int colBase = blockIdx.x * 128;
    const int warpRow = (wid & 1) * 64;
    const int warpCol = (wid >> 1) * 32;

    const fp16* srcs[2]  = {A, B};
    const int   rbase[2] = {rowBase, colBase};
    const int nch = K / GKC;

    const int aRowL = (lane & 7) + ((lane >> 3) & 1) * 8;
    const int aColL = (lane >> 4) * 8;
    const int bRowL = (lane & 7) + (lane >> 4) * 8;
    const int bColL = ((lane >> 3) & 1) * 8;

    float acc[4][4][4];
#pragma unroll
    for (int mt = 0; mt < 4; mt++)
#pragma unroll
        for (int nt = 0; nt < 4; nt++)
#pragma unroll
            for (int r = 0; r < 4; r++) acc[mt][nt][r] = 0.f;

    auto issue_chunk = [&](int chunk, int stage) {
        const uint32_t dbase = sb + stage * GBUF_B;
        const int gk = chunk * GKC;
#pragma unroll
        for (int i = 0; i < 8; i++) {
            const int tile = i >> 2;
            const int within = (i & 3) * 256 + tid;
            const int r = within >> 3, seg = within & 7;
            const fp16* gp = srcs[tile] + (size_t)(rbase[tile] + r) * K + gk + seg * 8;
            CP_ASYNC16(dbase + tile * GTILE_B + r * GLDS_B + seg * 16, gp);
        }
        CP_COMMIT();
    };

    issue_chunk(0, 0);
    issue_chunk(1, 1);

    for (int kc = 0; kc < nch; kc++) {
        if (kc + 1 < nch) { CP_WAIT1(); } else { CP_WAIT0(); }
        __syncthreads();

        const uint32_t cb = sb + (kc % GSTAGES) * GBUF_B;
        const uint32_t As = cb, Bs = cb + GTILE_B;

#pragma unroll
        for (int ks = 0; ks < 4; ks++) {
            const int kcol = ks * 16;
            uint32_t af[4][4], bf[2][4];
#pragma unroll
            for (int mt = 0; mt < 4; mt++) {
                const uint32_t off = (uint32_t)(warpRow + mt * 16 + aRowL) * GLDS_B
                                   + (uint32_t)(kcol + aColL) * 2;
                LDM_X4(af[mt][0], af[mt][1], af[mt][2], af[mt][3], As + off);
            }
#pragma unroll
            for (int ntp = 0; ntp < 2; ntp++) {
                const uint32_t off = (uint32_t)(warpCol + ntp * 16 + bRowL) * GLDS_B
                                   + (uint32_t)(kcol + bColL) * 2;
                LDM_X4(bf[ntp][0], bf[ntp][1], bf[ntp][2], bf[ntp][3], Bs + off);
            }
#pragma unroll
            for (int mt = 0; mt < 4; mt++)
#pragma unroll
                for (int nt = 0; nt < 4; nt++) {
                    const int ntp = nt >> 1, q = (nt & 1) * 2;
                    MMA_F16(acc[mt][nt], af[mt], bf[ntp][q], bf[ntp][q + 1]);
                }
        }

        if (kc + 2 < nch) issue_chunk(kc + 2, (kc + 2) % GSTAGES);
    }

    const int lr = lane >> 2, lc = (lane & 3) * 2;
#pragma unroll
    for (int mt = 0; mt < 4; mt++) {
#pragma unroll
        for (int nt = 0; nt < 4; nt++) {
            const int col = colBase + warpCol + nt * 8 + lc;
            const float sc = (col < scaleN) ? oscale : 1.0f;
            const float b0 = __ldg(&bias[col]);
            const float b1 = __ldg(&bias[col + 1]);
#pragma unroll
            for (int h = 0; h < 2; h++) {
                const int row = rowBase + warpRow + mt * 16 + lr + h * 8;
                float v0 = acc[mt][nt][2 * h]     + b0;
                float v1 = acc[mt][nt][2 * h + 1] + b1;
                if (relu) { v0 = fmaxf(v0, 0.f); v1 = fmaxf(v1, 0.f); }
                v0 *= sc; v1 *= sc;
                const size_t off = (size_t)row * N + col;
                if (C) *(float2*)(C + off) = make_float2(v0, v1);
                if (Ch) {
                    __half2 hh; hh.x = __float2half_rn(v0); hh.y = __float2half_rn(v1);
                    *(__half2*)(Ch + off) = hh;
                }
            }
        }
    }
}

// ---------------- tensor-core flash attention -----------------------------------------
#define FA_STR  72
#define FA_RB   (FA_STR*2)             // 144 B
#define FA_KVT  (64*FA_RB)             // 9216 B
#define FA_BUF  (2*FA_KVT)             // K,V
#define FA_SMEM (2*FA_BUF)             // 36864 B

template<bool CAUSAL>
__global__ __launch_bounds__(256)
void flash_tc(const fp16* __restrict__ Qh, const fp16* __restrict__ Kh,
              const fp16* __restrict__ Vh, fp16* __restrict__ Oh,
              int SK, int qstr, int kstr)
{
    extern __shared__ char smem[];
    const uint32_t sb = smem_u32(smem);
    const int tid = threadIdx.x;
    const int wid = tid >> 5, lane = tid & 31;
    const int b = blockIdx.z, h = blockIdx.y, qt = blockIdx.x;
    const int qbase = qt * 128;

    const size_t qoff = ((size_t)b * SEQ + qbase) * qstr + h * DKH;
    const size_t koff = (size_t)b * SK * kstr + h * DKH;

    {
        const fp16* qp = Qh + qoff;
#pragma unroll
        for (int i = 0; i < 4; i++) {
            const int idx = i * 256 + tid;
            const int r = idx >> 3, seg = idx & 7;
            CP_ASYNC16(sb + r * FA_RB + seg * 16, qp + (size_t)r * qstr + seg * 8);
        }
        CP_COMMIT();
        CP_WAIT0();
        __syncthreads();
    }

    const int aRowL = (lane & 7) + ((lane >> 3) & 1) * 8;
    const int aColL = (lane >> 4) * 8;
    uint32_t qf[4][4];
#pragma unroll
    for (int ks = 0; ks < 4; ks++) {
        const uint32_t off = (uint32_t)(wid * 16 + aRowL) * FA_RB + (uint32_t)(ks * 16 + aColL) * 2;
        LDM_X4(qf[ks][0], qf[ks][1], qf[ks][2], qf[ks][3], sb + off);
    }
    __syncthreads();

    float o[8][4];
#pragma unroll
    for (int dt = 0; dt < 8; dt++)
#pragma unroll
        for (int r = 0; r < 4; r++) o[dt][r] = 0.f;
    float m0 = -1e30f, m1 = -1e30f, l0 = 0.f, l1 = 0.f;

    const int r0g = qbase + wid * 16 + (lane >> 2);
    const int r1g = r0g + 8;
    const int nkt = CAUSAL ? (qt * 2 + 2) : (SK >> 6);

    {
#pragma unroll
        for (int i = 0; i < 2; i++) {
            const int idx = i * 256 + tid;
            const int r = idx >> 3, seg = idx & 7;
            const size_t g = koff + (size_t)r * kstr + seg * 8;
            CP_ASYNC16(sb + 0 * FA_KVT + r * FA_RB + seg * 16, Kh + g);
            CP_ASYNC16(sb + 1 * FA_KVT + r * FA_RB + seg * 16, Vh + g);
        }
        CP_COMMIT();
    }

    const int bRowL = (lane & 7) + (lane >> 4) * 8;
    const int bColL = ((lane >> 3) & 1) * 8;
    const int vRowL = lane & 15;
    const int vColL = (lane >> 4) * 8;

    for (int kt = 0; kt < nkt; kt++) {
        if (kt + 1 < nkt) {
            const uint32_t db = sb + ((kt + 1) & 1) * FA_BUF;
            const size_t kb = koff + (size_t)(kt + 1) * 64 * kstr;
#pragma unroll
            for (int i = 0; i < 2; i++) {
                const int idx = i * 256 + tid;
                const int r = idx >> 3, seg = idx & 7;
                const size_t g = kb + (size_t)r * kstr + seg * 8;
                CP_ASYNC16(db + 0 * FA_KVT + r * FA_RB + seg * 16, Kh + g);
                CP_ASYNC16(db + 1 * FA_KVT + r * FA_RB + seg * 16, Vh + g);
            }
            CP_COMMIT();
            CP_WAIT1();
        } else {
            CP_WAIT0();
        }
        __syncthreads();

        const uint32_t cb = sb + (kt & 1) * FA_BUF;
        const uint32_t Khs = cb, Vhs = cb + FA_KVT;

        float s[8][4];
#pragma unroll
        for (int nt = 0; nt < 8; nt++)
#pragma unroll
            for (int r = 0; r < 4; r++) s[nt][r] = 0.f;

#pragma unroll
        for (int ks = 0; ks < 4; ks++) {
#pragma unroll
            for (int np = 0; np < 4; np++) {
                uint32_t kf[4];
                const uint32_t off = (uint32_t)(np * 16 + bRowL) * FA_RB
                                   + (uint32_t)(ks * 16 + bColL) * 2;
                LDM_X4(kf[0], kf[1], kf[2], kf[3], Khs + off);
#pragma unroll
                for (int hf = 0; hf < 2; hf++) {
                    const int nt = np * 2 + hf, q = hf * 2;
                    MMA_F16(s[nt], qf[ks], kf[q], kf[q + 1]);
                }
            }
        }

        if (CAUSAL) {
            const int kb = kt * 64;
            if (kb + 63 > r0g) {
#pragma unroll
                for (int nt = 0; nt < 8; nt++)
#pragma unroll
                    for (int c = 0; c < 2; c++) {
                        const int key = kb + nt * 8 + ((lane & 3) << 1) + c;
                        if (key > r0g) s[nt][c]     = -1e30f;
                        if (key > r1g) s[nt][2 + c] = -1e30f;
                    }
            }
        }

        float mx0 = -1e30f, mx1 = -1e30f;
#pragma unroll
        for (int nt = 0; nt < 8; nt++) {
            mx0 = fmaxf(mx0, fmaxf(s[nt][0], s[nt][1]));
            mx1 = fmaxf(mx1, fmaxf(s[nt][2], s[nt][3]));
        }
        mx0 = fmaxf(mx0, __shfl_xor_sync(0xffffffffu, mx0, 1, 4));
        mx0 = fmaxf(mx0, __shfl_xor_sync(0xffffffffu, mx0, 2, 4));
        mx1 = fmaxf(mx1, __shfl_xor_sync(0xffffffffu, mx1, 1, 4));
        mx1 = fmaxf(mx1, __shfl_xor_sync(0xffffffffu, mx1, 2, 4));
        const float mn0 = fmaxf(m0, mx0), mn1 = fmaxf(m1, mx1);
        const float c0 = exp2f(m0 - mn0), c1 = exp2f(m1 - mn1);
        float rs0 = 0.f, rs1 = 0.f;
#pragma unroll
        for (int nt = 0; nt < 8; nt++) {
            s[nt][0] = exp2f(s[nt][0] - mn0);
            s[nt][1] = exp2f(s[nt][1] - mn0);
            s[nt][2] = exp2f(s[nt][2] - mn1);
            s[nt][3] = exp2f(s[nt][3] - mn1);
            rs0 += s[nt][0] + s[nt][1];
            rs1 += s[nt][2] + s[nt][3];
        }
        rs0 += __shfl_xor_sync(0xffffffffu, rs0, 1, 4);
        rs0 += __shfl_xor_sync(0xffffffffu, rs0, 2, 4);
        rs1 += __shfl_xor_sync(0xffffffffu, rs1, 1, 4);
        rs1 += __shfl_xor_sync(0xffffffffu, rs1, 2, 4);
        l0 = l0 * c0 + rs0; l1 = l1 * c1 + rs1;
        m0 = mn0; m1 = mn1;
#pragma unroll
        for (int dt = 0; dt < 8; dt++) {
            o[dt][0] *= c0; o[dt][1] *= c0;
            o[dt][2] *= c1; o[dt][3] *= c1;
        }

#pragma unroll
        for (int ks = 0; ks < 4; ks++) {
            const int nt0 = 2 * ks, nt1 = 2 * ks + 1;
            uint32_t pf[4];
            pf[0] = pack_h2(s[nt0][0], s[nt0][1]);
            pf[1] = pack_h2(s[nt0][2], s[nt0][3]);
            pf[2] = pack_h2(s[nt1][0], s[nt1][1]);
            pf[3] = pack_h2(s[nt1][2], s[nt1][3]);
#pragma unroll
            for (int dp = 0; dp < 4; dp++) {
                uint32_t vf[4];
                const uint32_t off = (uint32_t)(ks * 16 + vRowL) * FA_RB
                                   + (uint32_t)(dp * 16 + vColL) * 2;
                LDM_X4T(vf[0], vf[1], vf[2], vf[3], Vhs + off);
#pragma unroll
                for (int hf = 0; hf < 2; hf++) {
                    const int dt = dp * 2 + hf, q = hf * 2;
                    MMA_F16(o[dt], pf, vf[q], vf[q + 1]);
                }
            }
        }
        __syncthreads();
    }

    const float i0 = 1.f / l0, i1 = 1.f / l1;
    const int dcol = h * DKH + (lane & 3) * 2;
    const size_t ro0 = ((size_t)b * SEQ + r0g) * D_MODEL;
    const size_t ro1 = ((size_t)b * SEQ + r1g) * D_MODEL;
#pragma unroll
    for (int dt = 0; dt < 8; dt++) {
        const int dc = dcol + dt * 8;
        __half2 hh0; hh0.x = __float2half_rn(o[dt][0] * i0); hh0.y = __float2half_rn(o[dt][1] * i0);
        __half2 hh1; hh1.x = __float2half_rn(o[dt][2] * i1); hh1.y = __float2half_rn(o[dt][3] * i1);
        *(__half2*)(Oh + ro0 + dc) = hh0;
        *(__half2*)(Oh + ro1 + dc) = hh1;
    }
}

// ---------------- fused residual-add + LayerNorm (+ fp16 out) ------------------------
__global__ __launch_bounds__(256)
void add_ln_kernel(const float* __restrict__ X, const float* __restrict__ R,
                   const float* __restrict__ gamma, const float* __restrict__ beta,
                   float* __restrict__ Y, fp16* __restrict__ Yh)
{
    const int row = blockIdx.x;
    const int t = threadIdx.x;
    const float4 xv = ((const float4*)(X + (size_t)row * D_MODEL))[t];
    const float4 rv = ((const float4*)(R + (size_t)row * D_MODEL))[t];
    float v0 = xv.x + rv.x, v1 = xv.y + rv.y, v2 = xv.z + rv.z, v3 = xv.w + rv.w;

    float s  = v0 + v1 + v2 + v3;
    float ss = v0 * v0 + v1 * v1 + v2 * v2 + v3 * v3;
#pragma unroll
    for (int o = 16; o > 0; o >>= 1) {
        s  += __shfl_xor_sync(0xffffffffu, s,  o);
        ss += __shfl_xor_sync(0xffffffffu, ss, o);
    }
    __shared__ float sbuf[8], ssbuf[8];
    int w = t >> 5, ln = t & 31;
    if (ln == 0) { sbuf[w] = s; ssbuf[w] = ss; }
    __syncthreads();
    s = 0.f; ss = 0.f;
#pragma unroll
    for (int i = 0; i < 8; i++) { s += sbuf[i]; ss += ssbuf[i]; }

    const float mu  = s * (1.f / 1024.f);
    const float var = ss * (1.f / 1024.f) - mu * mu;
    const float rs  = rsqrtf(var + 1e-5f);
    const float4 gv = ((const float4*)gamma)[t];
    const float4 bv = ((const float4*)beta)[t];
    float4 o;
    o.x = (v0 - mu) * rs * gv.x + bv.x;
    o.y = (v1 - mu) * rs * gv.y + bv.y;
    o.z = (v2 - mu) * rs * gv.z + bv.z;
    o.w = (v3 - mu) * rs * gv.w + bv.w;
    ((float4*)(Y + (size_t)row * D_MODEL))[t] = o;

    if (Yh) {
        size_t off = (size_t)row * D_MODEL + t * 4;
        __half2 hh0; hh0.x = __float2half_rn(o.x); hh0.y = __float2half_rn(o.y);
        __half2 hh1; hh1.x = __float2half_rn(o.z); hh1.y = __float2half_rn(o.w);
        *(__half2*)(Yh + off)     = hh0;
        *(__half2*)(Yh + off + 2) = hh1;
    }
}

// ---------------- fp32 -> fp16 converts -----------------------------------------------
__global__ __launch_bounds__(256)
void cvt_kernel(const float4* __restrict__ src, __half2* __restrict__ dst, int n4)
{
    int i = blockIdx.x * blockDim.x + threadIdx.x;
    if (i >= n4) return;
    float4 v = src[i];
    __half2 a; a.x = __float2half_rn(v.x); a.y = __float2half_rn(v.y);
    __half2 b; b.x = __float2half_rn(v.z); b.y = __float2half_rn(v.w);
    dst[2 * i] = a; dst[2 * i + 1] = b;
}

// converts ALL weight matrices into the packed g_wh in one launch (4M float4 threads).
__global__ __launch_bounds__(256)
void cvt_w_kernel(const float4* w0, const float4* w1, const float4* w2, const float4* w3,
                  const float4* w4, const float4* w5, const float4* w6, const float4* w7,
                  const float4* wf1, const float4* wf2, __half2* __restrict__ dst)
{
    const int i = blockIdx.x * blockDim.x + threadIdx.x;
    const int S = MEG / 4;
    const int slot = i >> 18;
    const float4* src; int off;
    switch (slot) {
        case 0: src = w0; off = i;         break;
        case 1: src = w1; off = i - S;     break;
        case 2: src = w2; off = i - 2*S;   break;
        case 3: src = w3; off = i - 3*S;   break;
        case 4: src = w4; off = i - 4*S;   break;
        case 5: src = w5; off = i - 5*S;   break;
        case 6: src = w6; off = i - 6*S;   break;
        case 7: src = w7; off = i - 7*S;   break;
        case 8: case 9: case 10: case 11:
                src = wf1; off = i - 8*S;  break;
        default:
                src = wf2; off = i - 12*S; break;
    }
    float4 v = src[off];
    __half2 a; a.x = __float2half_rn(v.x); a.y = __float2half_rn(v.y);
    __half2 b; b.x = __float2half_rn(v.z); b.y = __float2half_rn(v.w);
    dst[2 * i] = a; dst[2 * i + 1] = b;
}

// ---------------- orchestration -------------------------------------------------------
static inline void gemm_on(cudaStream_t st, const fp16* A, const fp16* B, const float* bias,
                           float* C, fp16* Ch, int M, int N, int K, int relu,
                           float oscale = 1.0f, int scaleN = 0)
{
    dim3 g(N / 128, M / 128);
    gemm_tc<<<g, 256, GEMM_SMEM, st>>>(A, B, bias, C, Ch, M, N, K, relu, oscale, scaleN);
}

static inline void cvt_on(cudaStream_t st, const float* src, fp16* dst, int n)
{
    int n4 = n / 4;
    cvt_kernel<<<(n4 + 255) / 256, 256, 0, st>>>((const float4*)src, (__half2*)dst, n4);
}

extern "C" void kernel_launch(void* const* d_in, const int* in_sizes, int n_in,
                              void* d_out, int out_size)
{
    const float* x   = (const float*)d_in[0];
    const float* enc = (const float*)d_in[1];
    const float* Wq1 = (const float*)d_in[4],  *bq1 = (const float*)d_in[5];
    const float* Wk1 = (const float*)d_in[6],  *bk1 = (const float*)d_in[7];
    const float* Wv1 = (const float*)d_in[8],  *bv1 = (const float*)d_in[9];
    const float* Wo1 = (const float*)d_in[10], *bo1 = (const float*)d_in[11];
    const float* Wq2 = (const float*)d_in[12], *bq2 = (const float*)d_in[13];
    const float* Wk2 = (const float*)d_in[14], *bk2 = (const float*)d_in[15];
    const float* Wv2 = (const float*)d_in[16], *bv2 = (const float*)d_in[17];
    const float* Wo2 = (const float*)d_in[18], *bo2 = (const float*)d_in[19];
    const float* Wf1 = (const float*)d_in[20], *bf1 = (const float*)d_in[21];
    const float* Wf2 = (const float*)d_in[22], *bf2 = (const float*)d_in[23];
    const float* g1  = (const float*)d_in[24], *be1 = (const float*)d_in[25];
    const float* g2  = (const float*)d_in[26], *be2 = (const float*)d_in[27];
    const float* g3  = (const float*)d_in[28], *be3 = (const float*)d_in[29];
    float* out = (float*)d_out;

    const float QSCALE = 0.125f * 1.4426950408889634f;
    const cudaStream_t s0 = 0;   // legacy default stream (captured by harness)

    // one-time resources (created outside capture on the first/correctness call)
    static cudaStream_t s2 = nullptr;
    static cudaEvent_t evFork = nullptr, evJoin = nullptr;
    if (!s2) {
        cudaStreamCreateWithFlags(&s2, cudaStreamNonBlocking);
        cudaEventCreateWithFlags(&evFork, cudaEventDisableTiming);
        cudaEventCreateWithFlags(&evJoin, cudaEventDisableTiming);
        cudaFuncSetAttribute(gemm_tc, cudaFuncAttributeMaxDynamicSharedMemorySize, GEMM_SMEM);
        cudaFuncSetAttribute(flash_tc<true>,  cudaFuncAttributeMaxDynamicSharedMemorySize, FA_SMEM);
        cudaFuncSetAttribute(flash_tc<false>, cudaFuncAttributeMaxDynamicSharedMemorySize, FA_SMEM);
    }

    float *Ob, *X1, *X2, *bias3, *bias2;
    cudaGetSymbolAddress((void**)&Ob, g_bufO);
    cudaGetSymbolAddress((void**)&X1, g_bufX1);
    cudaGetSymbolAddress((void**)&X2, g_bufX2);
    cudaGetSymbolAddress((void**)&bias3, g_bias3);
    cudaGetSymbolAddress((void**)&bias2, g_bias2);
    fp16 *xh, *eh, *wh, *qkv, *q2, *kv2, *abh, *acth, *hh;
    cudaGetSymbolAddress((void**)&xh,   g_xh);
    cudaGetSymbolAddress((void**)&eh,   g_eh);
    cudaGetSymbolAddress((void**)&wh,   g_wh);
    cudaGetSymbolAddress((void**)&qkv,  g_qkv);
    cudaGetSymbolAddress((void**)&q2,   g_q2);
    cudaGetSymbolAddress((void**)&kv2,  g_kv2);
    cudaGetSymbolAddress((void**)&abh,  g_abh);
    cudaGetSymbolAddress((void**)&acth, g_acth);
    cudaGetSymbolAddress((void**)&hh,   g_hh);

    // packed weight slots (elements)
    const size_t OQKV1 = 0, OO1 = 3 * MEG, OQ2 = 4 * MEG, OKV2 = 5 * MEG, OO2 = 7 * MEG;
    const size_t OF1 = 8 * MEG, OF2 = 12 * MEG;

    // ---- front matter on main stream ----
    cvt_w_kernel<<<(4 * MEG) / 256, 256, 0, s0>>>(
        (const float4*)Wq1, (const float4*)Wk1, (const float4*)Wv1, (const float4*)Wo1,
        (const float4*)Wq2, (const float4*)Wk2, (const float4*)Wv2, (const float4*)Wo2,
        (const float4*)Wf1, (const float4*)Wf2, (__half2*)wh);
    cvt_on(s0, x, xh, ROWS * D_MODEL);
    cudaMemcpyAsync(bias3,             bq1, D_MODEL * 4, cudaMemcpyDeviceToDevice, s0);
    cudaMemcpyAsync(bias3 + D_MODEL,   bk1, D_MODEL * 4, cudaMemcpyDeviceToDevice, s0);
    cudaMemcpyAsync(bias3 + 2*D_MODEL, bv1, D_MODEL * 4, cudaMemcpyDeviceToDevice, s0);
    cudaMemcpyAsync(bias2,             bk2, D_MODEL * 4, cudaMemcpyDeviceToDevice, s0);
    cudaMemcpyAsync(bias2 + D_MODEL,   bv2, D_MODEL * 4, cudaMemcpyDeviceToDevice, s0);

    // ---- fork: cross-attn KV projection path on s2 (overlaps self-attention) ----
    cudaEventRecord(evFork, s0);
    cudaStreamWaitEvent(s2, evFork, 0);
    cvt_on(s2, enc, eh, ROWS * D_MODEL);
    gemm_on(s2, eh, wh + OKV2, bias2, 0, kv2, ROWS, 2 * D_MODEL, D_MODEL, 0);
    cudaEventRecord(evJoin, s2);

    dim3 gf(SEQ / 128, NHEAD, BATCH);

    // ---- self-attention (causal): fused QKV projection, N=3072 ----
    gemm_on(s0, xh, wh + OQKV1, bias3, 0, qkv, ROWS, 3 * D_MODEL, D_MODEL, 0, QSCALE, D_MODEL);
    flash_tc<true><<<gf, 256, FA_SMEM, s0>>>(qkv, qkv + D_MODEL, qkv + 2 * D_MODEL, abh,
                                             SEQ, 3 * D_MODEL, 3 * D_MODEL);
    gemm_on(s0, abh, wh + OO1, bo1, Ob, 0, ROWS, D_MODEL, D_MODEL, 0);
    add_ln_kernel<<<ROWS, 256, 0, s0>>>(x, Ob, g1, be1, X1, acth);

    // ---- cross-attention: Q projection on main, KV already in flight on s2 ----
    gemm_on(s0, acth, wh + OQ2, bq2, 0, q2, ROWS, D_MODEL, D_MODEL, 0, QSCALE, D_MODEL);
    cudaStreamWaitEvent(s0, evJoin, 0);
    flash_tc<false><<<gf, 256, FA_SMEM, s0>>>(q2, kv2, kv2 + D_MODEL, abh,
                                              SEQ, D_MODEL, 2 * D_MODEL);
    gemm_on(s0, abh, wh + OO2, bo2, Ob, 0, ROWS, D_MODEL, D_MODEL, 0);
    add_ln_kernel<<<ROWS, 256, 0, s0>>>(X1, Ob, g2, be2, X2, acth);

    // ---- FFN ----
    gemm_on(s0, acth, wh + OF1, bf1, 0, hh, ROWS, DFF, D_MODEL, 1);
    gemm_on(s0, hh, wh + OF2, bf2, Ob, 0, ROWS, D_MODEL, DFF, 0);
    add_ln_kernel<<<ROWS, 256, 0, s0>>>(X2, Ob, g3, be3, out, 0);
}

// round 13
// speedup vs baseline: 1.1035x; 1.0200x over previous
#include <cuda_runtime.h>
#include <cuda_fp16.h>
#include <cstdint>
#include <math.h>

#define D_MODEL 1024
#define SEQ     2048
#define BATCH   2
#define NHEAD   16
#define DKH     64
#define DFF     4096
#define ROWS    (BATCH*SEQ)   // 4096
#define MEG     (1024*1024)

typedef __half fp16;

// ---------------- scratch (static __device__ arrays; no allocation) ----------------
__device__ float g_bufO[ROWS*D_MODEL];
__device__ float g_bufX1[ROWS*D_MODEL];
__device__ float g_bufX2[ROWS*D_MODEL];
__device__ float g_bias3[3*D_MODEL];
__device__ float g_bias2[2*D_MODEL];

__device__ fp16 g_xh[ROWS*D_MODEL];
__device__ fp16 g_eh[ROWS*D_MODEL];
__device__ fp16 g_wh[16*MEG];
__device__ fp16 g_qkv[ROWS*3*D_MODEL];     // packed Q|K|V (self)
__device__ fp16 g_q2[ROWS*D_MODEL];
__device__ fp16 g_kv2[ROWS*2*D_MODEL];     // packed K|V (cross)
__device__ fp16 g_abh[ROWS*D_MODEL];
__device__ fp16 g_acth[ROWS*D_MODEL];
__device__ fp16 g_hh[ROWS*DFF];

// ---------------- PTX helpers ---------------------------------------------------------
__device__ __forceinline__ uint32_t smem_u32(const void* p) {
    uint32_t a;
    asm("{ .reg .u64 t; cvta.to.shared.u64 t, %1; cvt.u32.u64 %0, t; }" : "=r"(a) : "l"(p));
    return a;
}
#define CP_ASYNC16(dst, src) \
    asm volatile("cp.async.cg.shared.global [%0], [%1], 16;" :: "r"(dst), "l"(src))
#define CP_COMMIT()  asm volatile("cp.async.commit_group;" ::: "memory")
#define CP_WAIT1()   asm volatile("cp.async.wait_group 1;" ::: "memory")
#define CP_WAIT0()   asm volatile("cp.async.wait_group 0;" ::: "memory")

#define LDM_X4(r0, r1, r2, r3, addr) \
    asm volatile("ldmatrix.sync.aligned.m8n8.x4.shared.b16 {%0,%1,%2,%3}, [%4];" \
        : "=r"(r0), "=r"(r1), "=r"(r2), "=r"(r3) : "r"(addr))
#define LDM_X4T(r0, r1, r2, r3, addr) \
    asm volatile("ldmatrix.sync.aligned.m8n8.x4.trans.shared.b16 {%0,%1,%2,%3}, [%4];" \
        : "=r"(r0), "=r"(r1), "=r"(r2), "=r"(r3) : "r"(addr))

#define MMA_F16(c, a, b0, b1) \
    asm volatile("mma.sync.aligned.m16n8k16.row.col.f32.f16.f16.f32 " \
        "{%0,%1,%2,%3}, {%4,%5,%6,%7}, {%8,%9}, {%0,%1,%2,%3};" \
        : "+f"((c)[0]), "+f"((c)[1]), "+f"((c)[2]), "+f"((c)[3]) \
        : "r"((a)[0]), "r"((a)[1]), "r"((a)[2]), "r"((a)[3]), "r"(b0), "r"(b1))

__device__ __forceinline__ uint32_t pack_h2(float lo, float hi) {
    __half2 t; t.x = __float2half_rn(lo); t.y = __float2half_rn(hi);
    return *(uint32_t*)&t;
}

// ---------------- tensor-core GEMM: C[M,N] = A B^T + bias ----------------------------
// 128x128 CTA tile, 8 warps (64x32), KC=64, 3-stage cp.async ring, one sync per chunk.
#define GKC      64
#define GLDS_EL  72
#define GLDS_B   (GLDS_EL*2)        // 144 B
#define GTILE_B  (128*GLDS_B)       // 18432 B
#define GBUF_B   (2*GTILE_B)        // 36864 B per stage
#define GSTAGES  3
#define GEMM_SMEM (GSTAGES*GBUF_B)  // 110592 B

__global__ __launch_bounds__(256)
void gemm_tc(const fp16* __restrict__ A, const fp16* __restrict__ B,
             const float* __restrict__ bias, float* __restrict__ C,
             fp16* __restrict__ Ch,
             int M, int N, int K, int relu, float oscale, int scaleN)
{
    extern __shared__ char smem[];
    const uint32_t sb = smem_u32(smem);
    const int tid  = threadIdx.x;
    const int wid  = tid >> 5, lane = tid & 31;
    const int rowBase = blockIdx.y * 128;
    const int colBase = blockIdx.x * 128;
    const int warpRow = (wid & 1) * 64;
    const int warpCol = (wid >> 1) * 32;

    const fp16* srcs[2]  = {A, B};
    const int   rbase[2] = {rowBase, colBase};
    const int nch = K / GKC;

    const int aRowL = (lane & 7) + ((lane >> 3) & 1) * 8;
    const int aColL = (lane >> 4) * 8;
    const int bRowL = (lane & 7) + (lane >> 4) * 8;
    const int bColL = ((lane >> 3) & 1) * 8;

    float acc[4][4][4];
#pragma unroll
    for (int mt = 0; mt < 4; mt++)
#pragma unroll
        for (int nt = 0; nt < 4; nt++)
#pragma unroll
            for (int r = 0; r < 4; r++) acc[mt][nt][r] = 0.f;

    auto issue_chunk = [&](int chunk, int stage) {
        const uint32_t dbase = sb + stage * GBUF_B;
        const int gk = chunk * GKC;
#pragma unroll
        for (int i = 0; i < 8; i++) {
            const int tile = i >> 2;
            const int within = (i & 3) * 256 + tid;
            const int r = within >> 3, seg = within & 7;
            const fp16* gp = srcs[tile] + (size_t)(rbase[tile] + r) * K + gk + seg * 8;
            CP_ASYNC16(dbase + tile * GTILE_B + r * GLDS_B + seg * 16, gp);
        }
        CP_COMMIT();
    };

    issue_chunk(0, 0);
    issue_chunk(1, 1);

    for (int kc = 0; kc < nch; kc++) {
        if (kc + 1 < nch) { CP_WAIT1(); } else { CP_WAIT0(); }
        __syncthreads();

        const uint32_t cb = sb + (kc % GSTAGES) * GBUF_B;
        const uint32_t As = cb, Bs = cb + GTILE_B;

#pragma unroll
        for (int ks = 0; ks < 4; ks++) {
            const int kcol = ks * 16;
            uint32_t af[4][4], bf[2][4];
#pragma unroll
            for (int mt = 0; mt < 4; mt++) {
                const uint32_t off = (uint32_t)(warpRow + mt * 16 + aRowL) * GLDS_B
                                   + (uint32_t)(kcol + aColL) * 2;
                LDM_X4(af[mt][0], af[mt][1], af[mt][2], af[mt][3], As + off);
            }
#pragma unroll
            for (int ntp = 0; ntp < 2; ntp++) {
                const uint32_t off = (uint32_t)(warpCol + ntp * 16 + bRowL) * GLDS_B
                                   + (uint32_t)(kcol + bColL) * 2;
                LDM_X4(bf[ntp][0], bf[ntp][1], bf[ntp][2], bf[ntp][3], Bs + off);
            }
#pragma unroll
            for (int mt = 0; mt < 4; mt++)
#pragma unroll
                for (int nt = 0; nt < 4; nt++) {
                    const int ntp = nt >> 1, q = (nt & 1) * 2;
                    MMA_F16(acc[mt][nt], af[mt], bf[ntp][q], bf[ntp][q + 1]);
                }
        }

        if (kc + 2 < nch) issue_chunk(kc + 2, (kc + 2) % GSTAGES);
    }

    const int lr = lane >> 2, lc = (lane & 3) * 2;
#pragma unroll
    for (int mt = 0; mt < 4; mt++) {
#pragma unroll
        for (int nt = 0; nt < 4; nt++) {
            const int col = colBase + warpCol + nt * 8 + lc;
            const float sc = (col < scaleN) ? oscale : 1.0f;
            const float b0 = __ldg(&bias[col]);
            const float b1 = __ldg(&bias[col + 1]);
#pragma unroll
            for (int h = 0; h < 2; h++) {
                const int row = rowBase + warpRow + mt * 16 + lr + h * 8;
                float v0 = acc[mt][nt][2 * h]     + b0;
                float v1 = acc[mt][nt][2 * h + 1] + b1;
                if (relu) { v0 = fmaxf(v0, 0.f); v1 = fmaxf(v1, 0.f); }
                v0 *= sc; v1 *= sc;
                const size_t off = (size_t)row * N + col;
                if (C) *(float2*)(C + off) = make_float2(v0, v1);
                if (Ch) {
                    __half2 hh; hh.x = __float2half_rn(v0); hh.y = __float2half_rn(v1);
                    *(__half2*)(Ch + off) = hh;
                }
            }
        }
    }
}

// ---------------- tensor-core flash attention -----------------------------------------
// CAUSAL: grid.x = SEQ/256; each CTA processes paired q-tiles {bx, 2*gridDim.x-1-bx}
//         so per-CTA work is constant (load-balanced single wave).
// non-causal: grid.x = SEQ/128, one q-tile per CTA.
#define FA_STR  72
#define FA_RB   (FA_STR*2)             // 144 B
#define FA_KVT  (64*FA_RB)             // 9216 B
#define FA_BUF  (2*FA_KVT)             // K,V
#define FA_SMEM (2*FA_BUF)             // 36864 B

template<bool CAUSAL>
__global__ __launch_bounds__(256)
void flash_tc(const fp16* __restrict__ Qh, const fp16* __restrict__ Kh,
              const fp16* __restrict__ Vh, fp16* __restrict__ Oh,
              int SK, int qstr, int kstr)
{
    extern __shared__ char smem[];
    const uint32_t sb = smem_u32(smem);
    const int tid = threadIdx.x;
    const int wid = tid >> 5, lane = tid & 31;
    const int b = blockIdx.z, h = blockIdx.y;

    const int nrep = CAUSAL ? 2 : 1;
    for (int rep = 0; rep < nrep; rep++) {
        const int qt = CAUSAL ? (rep == 0 ? (int)blockIdx.x
                                          : (int)(2 * gridDim.x - 1 - blockIdx.x))
                              : (int)blockIdx.x;
        const int qbase = qt * 128;

        const size_t qoff = ((size_t)b * SEQ + qbase) * qstr + h * DKH;
        const size_t koff = (size_t)b * SK * kstr + h * DKH;

        // stage Q, build fragments, release smem
        {
            const fp16* qp = Qh + qoff;
#pragma unroll
            for (int i = 0; i < 4; i++) {
                const int idx = i * 256 + tid;
                const int r = idx >> 3, seg = idx & 7;
                CP_ASYNC16(sb + r * FA_RB + seg * 16, qp + (size_t)r * qstr + seg * 8);
            }
            CP_COMMIT();
            CP_WAIT0();
            __syncthreads();
        }

        const int aRowL = (lane & 7) + ((lane >> 3) & 1) * 8;
        const int aColL = (lane >> 4) * 8;
        uint32_t qf[4][4];
#pragma unroll
        for (int ks = 0; ks < 4; ks++) {
            const uint32_t off = (uint32_t)(wid * 16 + aRowL) * FA_RB
                               + (uint32_t)(ks * 16 + aColL) * 2;
            LDM_X4(qf[ks][0], qf[ks][1], qf[ks][2], qf[ks][3], sb + off);
        }
        __syncthreads();

        float o[8][4];
#pragma unroll
        for (int dt = 0; dt < 8; dt++)
#pragma unroll
            for (int r = 0; r < 4; r++) o[dt][r] = 0.f;
        float m0 = -1e30f, m1 = -1e30f, l0 = 0.f, l1 = 0.f;

        const int r0g = qbase + wid * 16 + (lane >> 2);
        const int r1g = r0g + 8;
        const int nkt = CAUSAL ? (qt * 2 + 2) : (SK >> 6);

        // prologue: tile 0 -> buf 0
        {
#pragma unroll
            for (int i = 0; i < 2; i++) {
                const int idx = i * 256 + tid;
                const int r = idx >> 3, seg = idx & 7;
                const size_t g = koff + (size_t)r * kstr + seg * 8;
                CP_ASYNC16(sb + 0 * FA_KVT + r * FA_RB + seg * 16, Kh + g);
                CP_ASYNC16(sb + 1 * FA_KVT + r * FA_RB + seg * 16, Vh + g);
            }
            CP_COMMIT();
        }

        const int bRowL = (lane & 7) + (lane >> 4) * 8;
        const int bColL = ((lane >> 3) & 1) * 8;
        const int vRowL = lane & 15;
        const int vColL = (lane >> 4) * 8;

        for (int kt = 0; kt < nkt; kt++) {
            if (kt + 1 < nkt) {
                const uint32_t db = sb + ((kt + 1) & 1) * FA_BUF;
                const size_t kb = koff + (size_t)(kt + 1) * 64 * kstr;
#pragma unroll
                for (int i = 0; i < 2; i++) {
                    const int idx = i * 256 + tid;
                    const int r = idx >> 3, seg = idx & 7;
                    const size_t g = kb + (size_t)r * kstr + seg * 8;
                    CP_ASYNC16(db + 0 * FA_KVT + r * FA_RB + seg * 16, Kh + g);
                    CP_ASYNC16(db + 1 * FA_KVT + r * FA_RB + seg * 16, Vh + g);
                }
                CP_COMMIT();
                CP_WAIT1();
            } else {
                CP_WAIT0();
            }
            __syncthreads();

            const uint32_t cb = sb + (kt & 1) * FA_BUF;
            const uint32_t Khs = cb, Vhs = cb + FA_KVT;

            float s[8][4];
#pragma unroll
            for (int nt = 0; nt < 8; nt++)
#pragma unroll
                for (int r = 0; r < 4; r++) s[nt][r] = 0.f;

#pragma unroll
            for (int ks = 0; ks < 4; ks++) {
#pragma unroll
                for (int np = 0; np < 4; np++) {
                    uint32_t kf[4];
                    const uint32_t off = (uint32_t)(np * 16 + bRowL) * FA_RB
                                       + (uint32_t)(ks * 16 + bColL) * 2;
                    LDM_X4(kf[0], kf[1], kf[2], kf[3], Khs + off);
#pragma unroll
                    for (int hf = 0; hf < 2; hf++) {
                        const int nt = np * 2 + hf, q = hf * 2;
                        MMA_F16(s[nt], qf[ks], kf[q], kf[q + 1]);
                    }
                }
            }

            if (CAUSAL) {
                const int kb = kt * 64;
                if (kb + 63 > r0g) {
#pragma unroll
                    for (int nt = 0; nt < 8; nt++)
#pragma unroll
                        for (int c = 0; c < 2; c++) {
                            const int key = kb + nt * 8 + ((lane & 3) << 1) + c;
                            if (key > r0g) s[nt][c]     = -1e30f;
                            if (key > r1g) s[nt][2 + c] = -1e30f;
                        }
                }
            }

            float mx0 = -1e30f, mx1 = -1e30f;
#pragma unroll
            for (int nt = 0; nt < 8; nt++) {
                mx0 = fmaxf(mx0, fmaxf(s[nt][0], s[nt][1]));
                mx1 = fmaxf(mx1, fmaxf(s[nt][2], s[nt][3]));
            }
            mx0 = fmaxf(mx0, __shfl_xor_sync(0xffffffffu, mx0, 1, 4));
            mx0 = fmaxf(mx0, __shfl_xor_sync(0xffffffffu, mx0, 2, 4));
            mx1 = fmaxf(mx1, __shfl_xor_sync(0xffffffffu, mx1, 1, 4));
            mx1 = fmaxf(mx1, __shfl_xor_sync(0xffffffffu, mx1, 2, 4));
            const float mn0 = fmaxf(m0, mx0), mn1 = fmaxf(m1, mx1);
            const float c0 = exp2f(m0 - mn0), c1 = exp2f(m1 - mn1);
            float rs0 = 0.f, rs1 = 0.f;
#pragma unroll
            for (int nt = 0; nt < 8; nt++) {
                s[nt][0] = exp2f(s[nt][0] - mn0);
                s[nt][1] = exp2f(s[nt][1] - mn0);
                s[nt][2] = exp2f(s[nt][2] - mn1);
                s[nt][3] = exp2f(s[nt][3] - mn1);
                rs0 += s[nt][0] + s[nt][1];
                rs1 += s[nt][2] + s[nt][3];
            }
            rs0 += __shfl_xor_sync(0xffffffffu, rs0, 1, 4);
            rs0 += __shfl_xor_sync(0xffffffffu, rs0, 2, 4);
            rs1 += __shfl_xor_sync(0xffffffffu, rs1, 1, 4);
            rs1 += __shfl_xor_sync(0xffffffffu, rs1, 2, 4);
            l0 = l0 * c0 + rs0; l1 = l1 * c1 + rs1;
            m0 = mn0; m1 = mn1;
#pragma unroll
            for (int dt = 0; dt < 8; dt++) {
                o[dt][0] *= c0; o[dt][1] *= c0;
                o[dt][2] *= c1; o[dt][3] *= c1;
            }

#pragma unroll
            for (int ks = 0; ks < 4; ks++) {
                const int nt0 = 2 * ks, nt1 = 2 * ks + 1;
                uint32_t pf[4];
                pf[0] = pack_h2(s[nt0][0], s[nt0][1]);
                pf[1] = pack_h2(s[nt0][2], s[nt0][3]);
                pf[2] = pack_h2(s[nt1][0], s[nt1][1]);
                pf[3] = pack_h2(s[nt1][2], s[nt1][3]);
#pragma unroll
                for (int dp = 0; dp < 4; dp++) {
                    uint32_t vf[4];
                    const uint32_t off = (uint32_t)(ks * 16 + vRowL) * FA_RB
                                       + (uint32_t)(dp * 16 + vColL) * 2;
                    LDM_X4T(vf[0], vf[1], vf[2], vf[3], Vhs + off);
#pragma unroll
                    for (int hf = 0; hf < 2; hf++) {
                        const int dt = dp * 2 + hf, q = hf * 2;
                        MMA_F16(o[dt], pf, vf[q], vf[q + 1]);
                    }
                }
            }
            __syncthreads();
        }

        const float i0 = 1.f / l0, i1 = 1.f / l1;
        const int dcol = h * DKH + (lane & 3) * 2;
        const size_t ro0 = ((size_t)b * SEQ + r0g) * D_MODEL;
        const size_t ro1 = ((size_t)b * SEQ + r1g) * D_MODEL;
#pragma unroll
        for (int dt = 0; dt < 8; dt++) {
            const int dc = dcol + dt * 8;
            __half2 hh0; hh0.x = __float2half_rn(o[dt][0] * i0); hh0.y = __float2half_rn(o[dt][1] * i0);
            __half2 hh1; hh1.x = __float2half_rn(o[dt][2] * i1); hh1.y = __float2half_rn(o[dt][3] * i1);
            *(__half2*)(Oh + ro0 + dc) = hh0;
            *(__half2*)(Oh + ro1 + dc) = hh1;
        }
    }
}

// ---------------- fused residual-add + LayerNorm (+ fp16 out) ------------------------
__global__ __launch_bounds__(256)
void add_ln_kernel(const float* __restrict__ X, const float* __restrict__ R,
                   const float* __restrict__ gamma, const float* __restrict__ beta,
                   float* __restrict__ Y, fp16* __restrict__ Yh)
{
    const int row = blockIdx.x;
    const int t = threadIdx.x;
    const float4 xv = ((const float4*)(X + (size_t)row * D_MODEL))[t];
    const float4 rv = ((const float4*)(R + (size_t)row * D_MODEL))[t];
    float v0 = xv.x + rv.x, v1 = xv.y + rv.y, v2 = xv.z + rv.z, v3 = xv.w + rv.w;

    float s  = v0 + v1 + v2 + v3;
    float ss = v0 * v0 + v1 * v1 + v2 * v2 + v3 * v3;
#pragma unroll
    for (int o = 16; o > 0; o >>= 1) {
        s  += __shfl_xor_sync(0xffffffffu, s,  o);
        ss += __shfl_xor_sync(0xffffffffu, ss, o);
    }
    __shared__ float sbuf[8], ssbuf[8];
    int w = t >> 5, ln = t & 31;
    if (ln == 0) { sbuf[w] = s; ssbuf[w] = ss; }
    __syncthreads();
    s = 0.f; ss = 0.f;
#pragma unroll
    for (int i = 0; i < 8; i++) { s += sbuf[i]; ss += ssbuf[i]; }

    const float mu  = s * (1.f / 1024.f);
    const float var = ss * (1.f / 1024.f) - mu * mu;
    const float rs  = rsqrtf(var + 1e-5f);
    const float4 gv = ((const float4*)gamma)[t];
    const float4 bv = ((const float4*)beta)[t];
    float4 o;
    o.x = (v0 - mu) * rs * gv.x + bv.x;
    o.y = (v1 - mu) * rs * gv.y + bv.y;
    o.z = (v2 - mu) * rs * gv.z + bv.z;
    o.w = (v3 - mu) * rs * gv.w + bv.w;
    ((float4*)(Y + (size_t)row * D_MODEL))[t] = o;

    if (Yh) {
        size_t off = (size_t)row * D_MODEL + t * 4;
        __half2 hh0; hh0.x = __float2half_rn(o.x); hh0.y = __float2half_rn(o.y);
        __half2 hh1; hh1.x = __float2half_rn(o.z); hh1.y = __float2half_rn(o.w);
        *(__half2*)(Yh + off)     = hh0;
        *(__half2*)(Yh + off + 2) = hh1;
    }
}

// ---------------- fp32 -> fp16 converts -----------------------------------------------
__global__ __launch_bounds__(256)
void cvt_kernel(const float4* __restrict__ src, __half2* __restrict__ dst, int n4)
{
    int i = blockIdx.x * blockDim.x + threadIdx.x;
    if (i >= n4) return;
    float4 v = src[i];
    __half2 a; a.x = __float2half_rn(v.x); a.y = __float2half_rn(v.y);
    __half2 b; b.x = __float2half_rn(v.z); b.y = __float2half_rn(v.w);
    dst[2 * i] = a; dst[2 * i + 1] = b;
}

// converts the 8 attention weight matrices (1M elements each) into packed g_wh[0..8M).
// Launched with 2*MEG threads (one per float4).
__global__ __launch_bounds__(256)
void cvt_w8_kernel(const float4* w0, const float4* w1, const float4* w2, const float4* w3,
                   const float4* w4, const float4* w5, const float4* w6, const float4* w7,
                   __half2* __restrict__ dst)
{
    const int i = blockIdx.x * blockDim.x + threadIdx.x;       // 0 .. 2M-1 float4s
    const int S = MEG / 4;                                     // 262144 float4 per MEG
    const int slot = i >> 18;
    const float4* src; int off;
    switch (slot) {
        case 0: src = w0; off = i;         break;
        case 1: src = w1; off = i - S;     break;
        case 2: src = w2; off = i - 2*S;   break;
        case 3: src = w3; off = i - 3*S;   break;
        case 4: src = w4; off = i - 4*S;   break;
        case 5: src = w5; off = i - 5*S;   break;
        case 6: src = w6; off = i - 6*S;   break;
        default: src = w7; off = i - 7*S;  break;
    }
    float4 v = src[off];
    __half2 a; a.x = __float2half_rn(v.x); a.y = __float2half_rn(v.y);
    __half2 b; b.x = __float2half_rn(v.z); b.y = __float2half_rn(v.w);
    dst[2 * i] = a; dst[2 * i + 1] = b;
}

// ---------------- orchestration -------------------------------------------------------
static inline void gemm_on(cudaStream_t st, const fp16* A, const fp16* B, const float* bias,
                           float* C, fp16* Ch, int M, int N, int K, int relu,
                           float oscale = 1.0f, int scaleN = 0)
{
    dim3 g(N / 128, M / 128);
    gemm_tc<<<g, 256, GEMM_SMEM, st>>>(A, B, bias, C, Ch, M, N, K, relu, oscale, scaleN);
}

static inline void cvt_on(cudaStream_t st, const float* src, fp16* dst, int n)
{
    int n4 = n / 4;
    cvt_kernel<<<(n4 + 255) / 256, 256, 0, st>>>((const float4*)src, (__half2*)dst, n4);
}

extern "C" void kernel_launch(void* const* d_in, const int* in_sizes, int n_in,
                              void* d_out, int out_size)
{
    const float* x   = (const float*)d_in[0];
    const float* enc = (const float*)d_in[1];
    const float* Wq1 = (const float*)d_in[4],  *bq1 = (const float*)d_in[5];
    const float* Wk1 = (const float*)d_in[6],  *bk1 = (const float*)d_in[7];
    const float* Wv1 = (const float*)d_in[8],  *bv1 = (const float*)d_in[9];
    const float* Wo1 = (const float*)d_in[10], *bo1 = (const float*)d_in[11];
    const float* Wq2 = (const float*)d_in[12], *bq2 = (const float*)d_in[13];
    const float* Wk2 = (const float*)d_in[14], *bk2 = (const float*)d_in[15];
    const float* Wv2 = (const float*)d_in[16], *bv2 = (const float*)d_in[17];
    const float* Wo2 = (const float*)d_in[18], *bo2 = (const float*)d_in[19];
    const float* Wf1 = (const float*)d_in[20], *bf1 = (const float*)d_in[21];
    const float* Wf2 = (const float*)d_in[22], *bf2 = (const float*)d_in[23];
    const float* g1  = (const float*)d_in[24], *be1 = (const float*)d_in[25];
    const float* g2  = (const float*)d_in[26], *be2 = (const float*)d_in[27];
    const float* g3  = (const float*)d_in[28], *be3 = (const float*)d_in[29];
    float* out = (float*)d_out;

    const float QSCALE = 0.125f * 1.4426950408889634f;
    const cudaStream_t s0 = 0;

    static cudaStream_t s2 = nullptr;
    static cudaEvent_t evFork = nullptr, evJoin = nullptr;
    if (!s2) {
        cudaStreamCreateWithFlags(&s2, cudaStreamNonBlocking);
        cudaEventCreateWithFlags(&evFork, cudaEventDisableTiming);
        cudaEventCreateWithFlags(&evJoin, cudaEventDisableTiming);
        cudaFuncSetAttribute(gemm_tc, cudaFuncAttributeMaxDynamicSharedMemorySize, GEMM_SMEM);
        cudaFuncSetAttribute(flash_tc<true>,  cudaFuncAttributeMaxDynamicSharedMemorySize, FA_SMEM);
        cudaFuncSetAttribute(flash_tc<false>, cudaFuncAttributeMaxDynamicSharedMemorySize, FA_SMEM);
    }

    float *Ob, *X1, *X2, *bias3, *bias2;
    cudaGetSymbolAddress((void**)&Ob, g_bufO);
    cudaGetSymbolAddress((void**)&X1, g_bufX1);
    cudaGetSymbolAddress((void**)&X2, g_bufX2);
    cudaGetSymbolAddress((void**)&bias3, g_bias3);
    cudaGetSymbolAddress((void**)&bias2, g_bias2);
    fp16 *xh, *eh, *wh, *qkv, *q2, *kv2, *abh, *acth, *hh;
    cudaGetSymbolAddress((void**)&xh,   g_xh);
    cudaGetSymbolAddress((void**)&eh,   g_eh);
    cudaGetSymbolAddress((void**)&wh,   g_wh);
    cudaGetSymbolAddress((void**)&qkv,  g_qkv);
    cudaGetSymbolAddress((void**)&q2,   g_q2);
    cudaGetSymbolAddress((void**)&kv2,  g_kv2);
    cudaGetSymbolAddress((void**)&abh,  g_abh);
    cudaGetSymbolAddress((void**)&acth, g_acth);
    cudaGetSymbolAddress((void**)&hh,   g_hh);

    const size_t OQKV1 = 0, OO1 = 3 * MEG, OQ2 = 4 * MEG, OKV2 = 5 * MEG, OO2 = 7 * MEG;
    const size_t OF1 = 8 * MEG, OF2 = 12 * MEG;

    // ---- front matter on main stream (attention weights only) ----
    cvt_w8_kernel<<<(2 * MEG) / 256, 256, 0, s0>>>(
        (const float4*)Wq1, (const float4*)Wk1, (const float4*)Wv1, (const float4*)Wo1,
        (const float4*)Wq2, (const float4*)Wk2, (const float4*)Wv2, (const float4*)Wo2,
        (__half2*)wh);
    cvt_on(s0, x, xh, ROWS * D_MODEL);
    cudaMemcpyAsync(bias3,             bq1, D_MODEL * 4, cudaMemcpyDeviceToDevice, s0);
    cudaMemcpyAsync(bias3 + D_MODEL,   bk1, D_MODEL * 4, cudaMemcpyDeviceToDevice, s0);
    cudaMemcpyAsync(bias3 + 2*D_MODEL, bv1, D_MODEL * 4, cudaMemcpyDeviceToDevice, s0);
    cudaMemcpyAsync(bias2,             bk2, D_MODEL * 4, cudaMemcpyDeviceToDevice, s0);
    cudaMemcpyAsync(bias2 + D_MODEL,   bv2, D_MODEL * 4, cudaMemcpyDeviceToDevice, s0);

    // ---- fork: FFN-weight converts + cross-attn KV path on s2 ----
    cudaEventRecord(evFork, s0);
    cudaStreamWaitEvent(s2, evFork, 0);
    cvt_on(s2, Wf1, wh + OF1, 4 * MEG);
    cvt_on(s2, Wf2, wh + OF2, 4 * MEG);
    cvt_on(s2, enc, eh, ROWS * D_MODEL);
    gemm_on(s2, eh, wh + OKV2, bias2, 0, kv2, ROWS, 2 * D_MODEL, D_MODEL, 0);
    cudaEventRecord(evJoin, s2);

    dim3 gf1(SEQ / 256, NHEAD, BATCH);   // causal: paired q-tiles
    dim3 gf2(SEQ / 128, NHEAD, BATCH);   // cross: one q-tile per CTA

    // ---- self-attention (causal): fused QKV projection, N=3072 ----
    gemm_on(s0, xh, wh + OQKV1, bias3, 0, qkv, ROWS, 3 * D_MODEL, D_MODEL, 0, QSCALE, D_MODEL);
    flash_tc<true><<<gf1, 256, FA_SMEM, s0>>>(qkv, qkv + D_MODEL, qkv + 2 * D_MODEL, abh,
                                              SEQ, 3 * D_MODEL, 3 * D_MODEL);
    gemm_on(s0, abh, wh + OO1, bo1, Ob, 0, ROWS, D_MODEL, D_MODEL, 0);
    add_ln_kernel<<<ROWS, 256, 0, s0>>>(x, Ob, g1, be1, X1, acth);

    // ---- cross-attention: Q projection on main, KV already in flight on s2 ----
    gemm_on(s0, acth, wh + OQ2, bq2, 0, q2, ROWS, D_MODEL, D_MODEL, 0, QSCALE, D_MODEL);
    cudaStreamWaitEvent(s0, evJoin, 0);
    flash_tc<false><<<gf2, 256, FA_SMEM, s0>>>(q2, kv2, kv2 + D_MODEL, abh,
                                               SEQ, D_MODEL, 2 * D_MODEL);
    gemm_on(s0, abh, wh + OO2, bo2, Ob, 0, ROWS, D_MODEL, D_MODEL, 0);
    add_ln_kernel<<<ROWS, 256, 0, s0>>>(X1, Ob, g2, be2, X2, acth);

    // ---- FFN ----
    gemm_on(s0, acth, wh + OF1, bf1, 0, hh, ROWS, DFF, D_MODEL, 1);
    gemm_on(s0, hh, wh + OF2, bf2, Ob, 0, ROWS, D_MODEL, DFF, 0);
    add_ln_kernel<<<ROWS, 256, 0, s0>>>(X2, Ob, g3, be3, out, 0);
}

// round 14
// speedup vs baseline: 1.1126x; 1.0083x over previous
#include <cuda_runtime.h>
#include <cuda_fp16.h>
#include <cstdint>
#include <math.h>

#define D_MODEL 1024
#define SEQ     2048
#define BATCH   2
#define NHEAD   16
#define DKH     64
#define DFF     4096
#define ROWS    (BATCH*SEQ)   // 4096
#define MEG     (1024*1024)

typedef __half fp16;

// ---------------- scratch (static __device__ arrays; no allocation) ----------------
__device__ float g_bufO[ROWS*D_MODEL];
__device__ float g_bufX1[ROWS*D_MODEL];
__device__ float g_bufX2[ROWS*D_MODEL];
__device__ float g_bias3[3*D_MODEL];
__device__ float g_bias2[2*D_MODEL];

__device__ fp16 g_xh[ROWS*D_MODEL];
__device__ fp16 g_eh[ROWS*D_MODEL];
__device__ fp16 g_wh[16*MEG];
__device__ fp16 g_qkv[ROWS*3*D_MODEL];     // packed Q|K|V (self)
__device__ fp16 g_q2[ROWS*D_MODEL];
__device__ fp16 g_kv2[ROWS*2*D_MODEL];     // packed K|V (cross)
__device__ fp16 g_abh[ROWS*D_MODEL];
__device__ fp16 g_acth[ROWS*D_MODEL];
__device__ fp16 g_hh[ROWS*DFF];

// ---------------- PTX helpers ---------------------------------------------------------
__device__ __forceinline__ uint32_t smem_u32(const void* p) {
    uint32_t a;
    asm("{ .reg .u64 t; cvta.to.shared.u64 t, %1; cvt.u32.u64 %0, t; }" : "=r"(a) : "l"(p));
    return a;
}
#define CP_ASYNC16(dst, src) \
    asm volatile("cp.async.cg.shared.global [%0], [%1], 16;" :: "r"(dst), "l"(src))
#define CP_COMMIT()  asm volatile("cp.async.commit_group;" ::: "memory")
#define CP_WAIT1()   asm volatile("cp.async.wait_group 1;" ::: "memory")
#define CP_WAIT0()   asm volatile("cp.async.wait_group 0;" ::: "memory")

#define LDM_X4(r0, r1, r2, r3, addr) \
    asm volatile("ldmatrix.sync.aligned.m8n8.x4.shared.b16 {%0,%1,%2,%3}, [%4];" \
        : "=r"(r0), "=r"(r1), "=r"(r2), "=r"(r3) : "r"(addr))
#define LDM_X4T(r0, r1, r2, r3, addr) \
    asm volatile("ldmatrix.sync.aligned.m8n8.x4.trans.shared.b16 {%0,%1,%2,%3}, [%4];" \
        : "=r"(r0), "=r"(r1), "=r"(r2), "=r"(r3) : "r"(addr))

#define MMA_F16(c, a, b0, b1) \
    asm volatile("mma.sync.aligned.m16n8k16.row.col.f32.f16.f16.f32 " \
        "{%0,%1,%2,%3}, {%4,%5,%6,%7}, {%8,%9}, {%0,%1,%2,%3};" \
        : "+f"((c)[0]), "+f"((c)[1]), "+f"((c)[2]), "+f"((c)[3]) \
        : "r"((a)[0]), "r"((a)[1]), "r"((a)[2]), "r"((a)[3]), "r"(b0), "r"(b1))

__device__ __forceinline__ uint32_t pack_h2(float lo, float hi) {
    __half2 t; t.x = __float2half_rn(lo); t.y = __float2half_rn(hi);
    return *(uint32_t*)&t;
}

// ---------------- tensor-core GEMM: C[M,N] = A B^T + bias ----------------------------
// 128x128 CTA tile, 8 warps (64x32), KC=64, 3-stage cp.async ring, one sync per chunk.
#define GKC      64
#define GLDS_EL  72
#define GLDS_B   (GLDS_EL*2)        // 144 B
#define GTILE_B  (128*GLDS_B)       // 18432 B
#define GBUF_B   (2*GTILE_B)        // 36864 B per stage
#define GSTAGES  3
#define GEMM_SMEM (GSTAGES*GBUF_B)  // 110592 B

__global__ __launch_bounds__(256)
void gemm_tc(const fp16* __restrict__ A, const fp16* __restrict__ B,
             const float* __restrict__ bias, float* __restrict__ C,
             fp16* __restrict__ Ch,
             int M, int N, int K, int relu, float oscale, int scaleN)
{
    extern __shared__ char smem[];
    const uint32_t sb = smem_u32(smem);
    const int tid  = threadIdx.x;
    const int wid  = tid >> 5, lane = tid & 31;
    const int rowBase = blockIdx.y * 128;
    const int colBase = blockIdx.x * 128;
    const int warpRow = (wid & 1) * 64;
    const int warpCol = (wid >> 1) * 32;

    const fp16* srcs[2]  = {A, B};
    const int   rbase[2] = {rowBase, colBase};
    const int nch = K / GKC;

    const int aRowL = (lane & 7) + ((lane >> 3) & 1) * 8;
    const int aColL = (lane >> 4) * 8;
    const int bRowL = (lane & 7) + (lane >> 4) * 8;
    const int bColL = ((lane >> 3) & 1) * 8;

    float acc[4][4][4];
#pragma unroll
    for (int mt = 0; mt < 4; mt++)
#pragma unroll
        for (int nt = 0; nt < 4; nt++)
#pragma unroll
            for (int r = 0; r < 4; r++) acc[mt][nt][r] = 0.f;

    auto issue_chunk = [&](int chunk, int stage) {
        const uint32_t dbase = sb + stage * GBUF_B;
        const int gk = chunk * GKC;
#pragma unroll
        for (int i = 0; i < 8; i++) {
            const int tile = i >> 2;
            const int within = (i & 3) * 256 + tid;
            const int r = within >> 3, seg = within & 7;
            const fp16* gp = srcs[tile] + (size_t)(rbase[tile] + r) * K + gk + seg * 8;
            CP_ASYNC16(dbase + tile * GTILE_B + r * GLDS_B + seg * 16, gp);
        }
        CP_COMMIT();
    };

    issue_chunk(0, 0);
    issue_chunk(1, 1);

    for (int kc = 0; kc < nch; kc++) {
        if (kc + 1 < nch) { CP_WAIT1(); } else { CP_WAIT0(); }
        __syncthreads();

        const uint32_t cb = sb + (kc % GSTAGES) * GBUF_B;
        const uint32_t As = cb, Bs = cb + GTILE_B;

#pragma unroll
        for (int ks = 0; ks < 4; ks++) {
            const int kcol = ks * 16;
            uint32_t af[4][4], bf[2][4];
#pragma unroll
            for (int mt = 0; mt < 4; mt++) {
                const uint32_t off = (uint32_t)(warpRow + mt * 16 + aRowL) * GLDS_B
                                   + (uint32_t)(kcol + aColL) * 2;
                LDM_X4(af[mt][0], af[mt][1], af[mt][2], af[mt][3], As + off);
            }
#pragma unroll
            for (int ntp = 0; ntp < 2; ntp++) {
                const uint32_t off = (uint32_t)(warpCol + ntp * 16 + bRowL) * GLDS_B
                                   + (uint32_t)(kcol + bColL) * 2;
                LDM_X4(bf[ntp][0], bf[ntp][1], bf[ntp][2], bf[ntp][3], Bs + off);
            }
#pragma unroll
            for (int mt = 0; mt < 4; mt++)
#pragma unroll
                for (int nt = 0; nt < 4; nt++) {
                    const int ntp = nt >> 1, q = (nt & 1) * 2;
                    MMA_F16(acc[mt][nt], af[mt], bf[ntp][q], bf[ntp][q + 1]);
                }
        }

        if (kc + 2 < nch) issue_chunk(kc + 2, (kc + 2) % GSTAGES);
    }

    const int lr = lane >> 2, lc = (lane & 3) * 2;
#pragma unroll
    for (int mt = 0; mt < 4; mt++) {
#pragma unroll
        for (int nt = 0; nt < 4; nt++) {
            const int col = colBase + warpCol + nt * 8 + lc;
            const float sc = (col < scaleN) ? oscale : 1.0f;
            const float b0 = __ldg(&bias[col]);
            const float b1 = __ldg(&bias[col + 1]);
#pragma unroll
            for (int h = 0; h < 2; h++) {
                const int row = rowBase + warpRow + mt * 16 + lr + h * 8;
                float v0 = acc[mt][nt][2 * h]     + b0;
                float v1 = acc[mt][nt][2 * h + 1] + b1;
                if (relu) { v0 = fmaxf(v0, 0.f); v1 = fmaxf(v1, 0.f); }
                v0 *= sc; v1 *= sc;
                const size_t off = (size_t)row * N + col;
                if (C) *(float2*)(C + off) = make_float2(v0, v1);
                if (Ch) {
                    __half2 hh; hh.x = __float2half_rn(v0); hh.y = __float2half_rn(v1);
                    *(__half2*)(Ch + off) = hh;
                }
            }
        }
    }
}

// ---------------- tensor-core flash attention -----------------------------------------
// CAUSAL: grid.x = SEQ/256; each CTA processes paired q-tiles {bx, 2*gridDim.x-1-bx}.
// non-causal: grid.x = SEQ/128, one q-tile per CTA.
#define FA_STR  72
#define FA_RB   (FA_STR*2)             // 144 B
#define FA_KVT  (64*FA_RB)             // 9216 B
#define FA_BUF  (2*FA_KVT)             // K,V
#define FA_SMEM (2*FA_BUF)             // 36864 B

template<bool CAUSAL>
__global__ __launch_bounds__(256)
void flash_tc(const fp16* __restrict__ Qh, const fp16* __restrict__ Kh,
              const fp16* __restrict__ Vh, fp16* __restrict__ Oh,
              int SK, int qstr, int kstr)
{
    extern __shared__ char smem[];
    const uint32_t sb = smem_u32(smem);
    const int tid = threadIdx.x;
    const int wid = tid >> 5, lane = tid & 31;
    const int b = blockIdx.z, h = blockIdx.y;

    const int nrep = CAUSAL ? 2 : 1;
    for (int rep = 0; rep < nrep; rep++) {
        const int qt = CAUSAL ? (rep == 0 ? (int)blockIdx.x
                                          : (int)(2 * gridDim.x - 1 - blockIdx.x))
                              : (int)blockIdx.x;
        const int qbase = qt * 128;

        const size_t qoff = ((size_t)b * SEQ + qbase) * qstr + h * DKH;
        const size_t koff = (size_t)b * SK * kstr + h * DKH;

        // stage Q, build fragments, release smem
        {
            const fp16* qp = Qh + qoff;
#pragma unroll
            for (int i = 0; i < 4; i++) {
                const int idx = i * 256 + tid;
                const int r = idx >> 3, seg = idx & 7;
                CP_ASYNC16(sb + r * FA_RB + seg * 16, qp + (size_t)r * qstr + seg * 8);
            }
            CP_COMMIT();
            CP_WAIT0();
            __syncthreads();
        }

        const int aRowL = (lane & 7) + ((lane >> 3) & 1) * 8;
        const int aColL = (lane >> 4) * 8;
        uint32_t qf[4][4];
#pragma unroll
        for (int ks = 0; ks < 4; ks++) {
            const uint32_t off = (uint32_t)(wid * 16 + aRowL) * FA_RB
                               + (uint32_t)(ks * 16 + aColL) * 2;
            LDM_X4(qf[ks][0], qf[ks][1], qf[ks][2], qf[ks][3], sb + off);
        }
        __syncthreads();

        float o[8][4];
#pragma unroll
        for (int dt = 0; dt < 8; dt++)
#pragma unroll
            for (int r = 0; r < 4; r++) o[dt][r] = 0.f;
        float m0 = -1e30f, m1 = -1e30f, l0 = 0.f, l1 = 0.f;

        const int r0g = qbase + wid * 16 + (lane >> 2);
        const int r1g = r0g + 8;
        const int nkt = CAUSAL ? (qt * 2 + 2) : (SK >> 6);

        // prologue: tile 0 -> buf 0
        {
#pragma unroll
            for (int i = 0; i < 2; i++) {
                const int idx = i * 256 + tid;
                const int r = idx >> 3, seg = idx & 7;
                const size_t g = koff + (size_t)r * kstr + seg * 8;
                CP_ASYNC16(sb + 0 * FA_KVT + r * FA_RB + seg * 16, Kh + g);
                CP_ASYNC16(sb + 1 * FA_KVT + r * FA_RB + seg * 16, Vh + g);
            }
            CP_COMMIT();
        }

        const int bRowL = (lane & 7) + (lane >> 4) * 8;
        const int bColL = ((lane >> 3) & 1) * 8;
        const int vRowL = lane & 15;
        const int vColL = (lane >> 4) * 8;

        for (int kt = 0; kt < nkt; kt++) {
            if (kt + 1 < nkt) {
                const uint32_t db = sb + ((kt + 1) & 1) * FA_BUF;
                const size_t kb = koff + (size_t)(kt + 1) * 64 * kstr;
#pragma unroll
                for (int i = 0; i < 2; i++) {
                    const int idx = i * 256 + tid;
                    const int r = idx >> 3, seg = idx & 7;
                    const size_t g = kb + (size_t)r * kstr + seg * 8;
                    CP_ASYNC16(db + 0 * FA_KVT + r * FA_RB + seg * 16, Kh + g);
                    CP_ASYNC16(db + 1 * FA_KVT + r * FA_RB + seg * 16, Vh + g);
                }
                CP_COMMIT();
                CP_WAIT1();
            } else {
                CP_WAIT0();
            }
            __syncthreads();

            const uint32_t cb = sb + (kt & 1) * FA_BUF;
            const uint32_t Khs = cb, Vhs = cb + FA_KVT;

            float s[8][4];
#pragma unroll
            for (int nt = 0; nt < 8; nt++)
#pragma unroll
                for (int r = 0; r < 4; r++) s[nt][r] = 0.f;

#pragma unroll
            for (int ks = 0; ks < 4; ks++) {
#pragma unroll
                for (int np = 0; np < 4; np++) {
                    uint32_t kf[4];
                    const uint32_t off = (uint32_t)(np * 16 + bRowL) * FA_RB
                                       + (uint32_t)(ks * 16 + bColL) * 2;
                    LDM_X4(kf[0], kf[1], kf[2], kf[3], Khs + off);
#pragma unroll
                    for (int hf = 0; hf < 2; hf++) {
                        const int nt = np * 2 + hf, q = hf * 2;
                        MMA_F16(s[nt], qf[ks], kf[q], kf[q + 1]);
                    }
                }
            }

            if (CAUSAL) {
                const int kb = kt * 64;
                if (kb + 63 > r0g) {
#pragma unroll
                    for (int nt = 0; nt < 8; nt++)
#pragma unroll
                        for (int c = 0; c < 2; c++) {
                            const int key = kb + nt * 8 + ((lane & 3) << 1) + c;
                            if (key > r0g) s[nt][c]     = -1e30f;
                            if (key > r1g) s[nt][2 + c] = -1e30f;
                        }
                }
            }

            float mx0 = -1e30f, mx1 = -1e30f;
#pragma unroll
            for (int nt = 0; nt < 8; nt++) {
                mx0 = fmaxf(mx0, fmaxf(s[nt][0], s[nt][1]));
                mx1 = fmaxf(mx1, fmaxf(s[nt][2], s[nt][3]));
            }
            mx0 = fmaxf(mx0, __shfl_xor_sync(0xffffffffu, mx0, 1, 4));
            mx0 = fmaxf(mx0, __shfl_xor_sync(0xffffffffu, mx0, 2, 4));
            mx1 = fmaxf(mx1, __shfl_xor_sync(0xffffffffu, mx1, 1, 4));
            mx1 = fmaxf(mx1, __shfl_xor_sync(0xffffffffu, mx1, 2, 4));
            const float mn0 = fmaxf(m0, mx0), mn1 = fmaxf(m1, mx1);
            const float c0 = exp2f(m0 - mn0), c1 = exp2f(m1 - mn1);
            float rs0 = 0.f, rs1 = 0.f;
#pragma unroll
            for (int nt = 0; nt < 8; nt++) {
                s[nt][0] = exp2f(s[nt][0] - mn0);
                s[nt][1] = exp2f(s[nt][1] - mn0);
                s[nt][2] = exp2f(s[nt][2] - mn1);
                s[nt][3] = exp2f(s[nt][3] - mn1);
                rs0 += s[nt][0] + s[nt][1];
                rs1 += s[nt][2] + s[nt][3];
            }
            rs0 += __shfl_xor_sync(0xffffffffu, rs0, 1, 4);
            rs0 += __shfl_xor_sync(0xffffffffu, rs0, 2, 4);
            rs1 += __shfl_xor_sync(0xffffffffu, rs1, 1, 4);
            rs1 += __shfl_xor_sync(0xffffffffu, rs1, 2, 4);
            l0 = l0 * c0 + rs0; l1 = l1 * c1 + rs1;
            m0 = mn0; m1 = mn1;
#pragma unroll
            for (int dt = 0; dt < 8; dt++) {
                o[dt][0] *= c0; o[dt][1] *= c0;
                o[dt][2] *= c1; o[dt][3] *= c1;
            }

#pragma unroll
            for (int ks = 0; ks < 4; ks++) {
                const int nt0 = 2 * ks, nt1 = 2 * ks + 1;
                uint32_t pf[4];
                pf[0] = pack_h2(s[nt0][0], s[nt0][1]);
                pf[1] = pack_h2(s[nt0][2], s[nt0][3]);
                pf[2] = pack_h2(s[nt1][0], s[nt1][1]);
                pf[3] = pack_h2(s[nt1][2], s[nt1][3]);
#pragma unroll
                for (int dp = 0; dp < 4; dp++) {
                    uint32_t vf[4];
                    const uint32_t off = (uint32_t)(ks * 16 + vRowL) * FA_RB
                                       + (uint32_t)(dp * 16 + vColL) * 2;
                    LDM_X4T(vf[0], vf[1], vf[2], vf[3], Vhs + off);
#pragma unroll
                    for (int hf = 0; hf < 2; hf++) {
                        const int dt = dp * 2 + hf, q = hf * 2;
                        MMA_F16(o[dt], pf, vf[q], vf[q + 1]);
                    }
                }
            }
            __syncthreads();
        }

        const float i0 = 1.f / l0, i1 = 1.f / l1;
        const int dcol = h * DKH + (lane & 3) * 2;
        const size_t ro0 = ((size_t)b * SEQ + r0g) * D_MODEL;
        const size_t ro1 = ((size_t)b * SEQ + r1g) * D_MODEL;
#pragma unroll
        for (int dt = 0; dt < 8; dt++) {
            const int dc = dcol + dt * 8;
            __half2 hh0; hh0.x = __float2half_rn(o[dt][0] * i0); hh0.y = __float2half_rn(o[dt][1] * i0);
            __half2 hh1; hh1.x = __float2half_rn(o[dt][2] * i1); hh1.y = __float2half_rn(o[dt][3] * i1);
            *(__half2*)(Oh + ro0 + dc) = hh0;
            *(__half2*)(Oh + ro1 + dc) = hh1;
        }
    }
}

// ---------------- fused residual-add + LayerNorm (+ fp16 out) ------------------------
__global__ __launch_bounds__(256)
void add_ln_kernel(const float* __restrict__ X, const float* __restrict__ R,
                   const float* __restrict__ gamma, const float* __restrict__ beta,
                   float* __restrict__ Y, fp16* __restrict__ Yh)
{
    const int row = blockIdx.x;
    const int t = threadIdx.x;
    const float4 xv = ((const float4*)(X + (size_t)row * D_MODEL))[t];
    const float4 rv = ((const float4*)(R + (size_t)row * D_MODEL))[t];
    float v0 = xv.x + rv.x, v1 = xv.y + rv.y, v2 = xv.z + rv.z, v3 = xv.w + rv.w;

    float s  = v0 + v1 + v2 + v3;
    float ss = v0 * v0 + v1 * v1 + v2 * v2 + v3 * v3;
#pragma unroll
    for (int o = 16; o > 0; o >>= 1) {
        s  += __shfl_xor_sync(0xffffffffu, s,  o);
        ss += __shfl_xor_sync(0xffffffffu, ss, o);
    }
    __shared__ float sbuf[8], ssbuf[8];
    int w = t >> 5, ln = t & 31;
    if (ln == 0) { sbuf[w] = s; ssbuf[w] = ss; }
    __syncthreads();
    s = 0.f; ss = 0.f;
#pragma unroll
    for (int i = 0; i < 8; i++) { s += sbuf[i]; ss += ssbuf[i]; }

    const float mu  = s * (1.f / 1024.f);
    const float var = ss * (1.f / 1024.f) - mu * mu;
    const float rs  = rsqrtf(var + 1e-5f);
    const float4 gv = ((const float4*)gamma)[t];
    const float4 bv = ((const float4*)beta)[t];
    float4 o;
    o.x = (v0 - mu) * rs * gv.x + bv.x;
    o.y = (v1 - mu) * rs * gv.y + bv.y;
    o.z = (v2 - mu) * rs * gv.z + bv.z;
    o.w = (v3 - mu) * rs * gv.w + bv.w;
    ((float4*)(Y + (size_t)row * D_MODEL))[t] = o;

    if (Yh) {
        size_t off = (size_t)row * D_MODEL + t * 4;
        __half2 hh0; hh0.x = __float2half_rn(o.x); hh0.y = __float2half_rn(o.y);
        __half2 hh1; hh1.x = __float2half_rn(o.z); hh1.y = __float2half_rn(o.w);
        *(__half2*)(Yh + off)     = hh0;
        *(__half2*)(Yh + off + 2) = hh1;
    }
}

// ---------------- fp32 -> fp16 converts -----------------------------------------------
__global__ __launch_bounds__(256)
void cvt_kernel(const float4* __restrict__ src, __half2* __restrict__ dst, int n4)
{
    int i = blockIdx.x * blockDim.x + threadIdx.x;
    if (i >= n4) return;
    float4 v = src[i];
    __half2 a; a.x = __float2half_rn(v.x); a.y = __float2half_rn(v.y);
    __half2 b; b.x = __float2half_rn(v.z); b.y = __float2half_rn(v.w);
    dst[2 * i] = a; dst[2 * i + 1] = b;
}

// converts 5 attention weight matrices (Wq1,Wk1,Wv1,Wo1,Wq2) into g_wh[0..5M).
// Launched with 5*MEG/4 threads (one per float4).
__global__ __launch_bounds__(256)
void cvt_w5_kernel(const float4* w0, const float4* w1, const float4* w2, const float4* w3,
                   const float4* w4, __half2* __restrict__ dst)
{
    const int i = blockIdx.x * blockDim.x + threadIdx.x;       // 0 .. 5*S-1 float4s
    const int S = MEG / 4;                                     // 262144 float4 per MEG
    const int slot = i >> 18;
    const float4* src; int off;
    switch (slot) {
        case 0: src = w0; off = i;         break;
        case 1: src = w1; off = i - S;     break;
        case 2: src = w2; off = i - 2*S;   break;
        case 3: src = w3; off = i - 3*S;   break;
        default: src = w4; off = i - 4*S;  break;
    }
    float4 v = src[off];
    __half2 a; a.x = __float2half_rn(v.x); a.y = __float2half_rn(v.y);
    __half2 b; b.x = __float2half_rn(v.z); b.y = __float2half_rn(v.w);
    dst[2 * i] = a; dst[2 * i + 1] = b;
}

// ---------------- orchestration -------------------------------------------------------
static inline void gemm_on(cudaStream_t st, const fp16* A, const fp16* B, const float* bias,
                           float* C, fp16* Ch, int M, int N, int K, int relu,
                           float oscale = 1.0f, int scaleN = 0)
{
    dim3 g(N / 128, M / 128);
    gemm_tc<<<g, 256, GEMM_SMEM, st>>>(A, B, bias, C, Ch, M, N, K, relu, oscale, scaleN);
}

static inline void cvt_on(cudaStream_t st, const float* src, fp16* dst, int n)
{
    int n4 = n / 4;
    cvt_kernel<<<(n4 + 255) / 256, 256, 0, st>>>((const float4*)src, (__half2*)dst, n4);
}

extern "C" void kernel_launch(void* const* d_in, const int* in_sizes, int n_in,
                              void* d_out, int out_size)
{
    const float* x   = (const float*)d_in[0];
    const float* enc = (const float*)d_in[1];
    const float* Wq1 = (const float*)d_in[4],  *bq1 = (const float*)d_in[5];
    const float* Wk1 = (const float*)d_in[6],  *bk1 = (const float*)d_in[7];
    const float* Wv1 = (const float*)d_in[8],  *bv1 = (const float*)d_in[9];
    const float* Wo1 = (const float*)d_in[10], *bo1 = (const float*)d_in[11];
    const float* Wq2 = (const float*)d_in[12], *bq2 = (const float*)d_in[13];
    const float* Wk2 = (const float*)d_in[14], *bk2 = (const float*)d_in[15];
    const float* Wv2 = (const float*)d_in[16], *bv2 = (const float*)d_in[17];
    const float* Wo2 = (const float*)d_in[18], *bo2 = (const float*)d_in[19];
    const float* Wf1 = (const float*)d_in[20], *bf1 = (const float*)d_in[21];
    const float* Wf2 = (const float*)d_in[22], *bf2 = (const float*)d_in[23];
    const float* g1  = (const float*)d_in[24], *be1 = (const float*)d_in[25];
    const float* g2  = (const float*)d_in[26], *be2 = (const float*)d_in[27];
    const float* g3  = (const float*)d_in[28], *be3 = (const float*)d_in[29];
    float* out = (float*)d_out;

    const float QSCALE = 0.125f * 1.4426950408889634f;
    const cudaStream_t s0 = 0;

    static cudaStream_t s2 = nullptr;
    static cudaEvent_t evFork = nullptr, evJoin = nullptr;
    if (!s2) {
        cudaStreamCreateWithFlags(&s2, cudaStreamNonBlocking);
        cudaEventCreateWithFlags(&evFork, cudaEventDisableTiming);
        cudaEventCreateWithFlags(&evJoin, cudaEventDisableTiming);
        cudaFuncSetAttribute(gemm_tc, cudaFuncAttributeMaxDynamicSharedMemorySize, GEMM_SMEM);
        cudaFuncSetAttribute(flash_tc<true>,  cudaFuncAttributeMaxDynamicSharedMemorySize, FA_SMEM);
        cudaFuncSetAttribute(flash_tc<false>, cudaFuncAttributeMaxDynamicSharedMemorySize, FA_SMEM);
    }

    float *Ob, *X1, *X2, *bias3, *bias2;
    cudaGetSymbolAddress((void**)&Ob, g_bufO);
    cudaGetSymbolAddress((void**)&X1, g_bufX1);
    cudaGetSymbolAddress((void**)&X2, g_bufX2);
    cudaGetSymbolAddress((void**)&bias3, g_bias3);
    cudaGetSymbolAddress((void**)&bias2, g_bias2);
    fp16 *xh, *eh, *wh, *qkv, *q2, *kv2, *abh, *acth, *hh;
    cudaGetSymbolAddress((void**)&xh,   g_xh);
    cudaGetSymbolAddress((void**)&eh,   g_eh);
    cudaGetSymbolAddress((void**)&wh,   g_wh);
    cudaGetSymbolAddress((void**)&qkv,  g_qkv);
    cudaGetSymbolAddress((void**)&q2,   g_q2);
    cudaGetSymbolAddress((void**)&kv2,  g_kv2);
    cudaGetSymbolAddress((void**)&abh,  g_abh);
    cudaGetSymbolAddress((void**)&acth, g_acth);
    cudaGetSymbolAddress((void**)&hh,   g_hh);

    // packed weight slots (elements): QKV1 at 0, O1 at 3M, Q2 at 4M, KV2 at 5M, O2 at 7M
    const size_t OQKV1 = 0, OO1 = 3 * MEG, OQ2 = 4 * MEG, OKV2 = 5 * MEG, OO2 = 7 * MEG;
    const size_t OF1 = 8 * MEG, OF2 = 12 * MEG;

    // ---- front matter on main stream: only weights s0 itself needs pre-join ----
    cvt_w5_kernel<<<(5 * MEG / 4) / 256, 256, 0, s0>>>(
        (const float4*)Wq1, (const float4*)Wk1, (const float4*)Wv1, (const float4*)Wo1,
        (const float4*)Wq2, (__half2*)wh);
    cvt_on(s0, x, xh, ROWS * D_MODEL);
    cudaMemcpyAsync(bias3,             bq1, D_MODEL * 4, cudaMemcpyDeviceToDevice, s0);
    cudaMemcpyAsync(bias3 + D_MODEL,   bk1, D_MODEL * 4, cudaMemcpyDeviceToDevice, s0);
    cudaMemcpyAsync(bias3 + 2*D_MODEL, bv1, D_MODEL * 4, cudaMemcpyDeviceToDevice, s0);
    cudaMemcpyAsync(bias2,             bk2, D_MODEL * 4, cudaMemcpyDeviceToDevice, s0);
    cudaMemcpyAsync(bias2 + D_MODEL,   bv2, D_MODEL * 4, cudaMemcpyDeviceToDevice, s0);

    // ---- fork: Wk2/Wv2/Wo2 + FFN weight converts + cross-attn KV path on s2 ----
    cudaEventRecord(evFork, s0);
    cudaStreamWaitEvent(s2, evFork, 0);
    cvt_on(s2, Wk2, wh + OKV2, MEG);
    cvt_on(s2, Wv2, wh + OKV2 + MEG, MEG);
    cvt_on(s2, Wo2, wh + OO2, MEG);
    cvt_on(s2, Wf1, wh + OF1, 4 * MEG);
    cvt_on(s2, Wf2, wh + OF2, 4 * MEG);
    cvt_on(s2, enc, eh, ROWS * D_MODEL);
    gemm_on(s2, eh, wh + OKV2, bias2, 0, kv2, ROWS, 2 * D_MODEL, D_MODEL, 0);
    cudaEventRecord(evJoin, s2);

    dim3 gf1(SEQ / 256, NHEAD, BATCH);   // causal: paired q-tiles
    dim3 gf2(SEQ / 128, NHEAD, BATCH);   // cross: one q-tile per CTA

    // ---- self-attention (causal): fused QKV projection, N=3072 ----
    gemm_on(s0, xh, wh + OQKV1, bias3, 0, qkv, ROWS, 3 * D_MODEL, D_MODEL, 0, QSCALE, D_MODEL);
    flash_tc<true><<<gf1, 256, FA_SMEM, s0>>>(qkv, qkv + D_MODEL, qkv + 2 * D_MODEL, abh,
                                              SEQ, 3 * D_MODEL, 3 * D_MODEL);
    gemm_on(s0, abh, wh + OO1, bo1, Ob, 0, ROWS, D_MODEL, D_MODEL, 0);
    add_ln_kernel<<<ROWS, 256, 0, s0>>>(x, Ob, g1, be1, X1, acth);

    // ---- cross-attention: Q projection on main, KV already in flight on s2 ----
    gemm_on(s0, acth, wh + OQ2, bq2, 0, q2, ROWS, D_MODEL, D_MODEL, 0, QSCALE, D_MODEL);
    cudaStreamWaitEvent(s0, evJoin, 0);
    flash_tc<false><<<gf2, 256, FA_SMEM, s0>>>(q2, kv2, kv2 + D_MODEL, abh,
                                               SEQ, D_MODEL, 2 * D_MODEL);
    gemm_on(s0, abh, wh + OO2, bo2, Ob, 0, ROWS, D_MODEL, D_MODEL, 0);
    add_ln_kernel<<<ROWS, 256, 0, s0>>>(X1, Ob, g2, be2, X2, acth);

    // ---- FFN ----
    gemm_on(s0, acth, wh + OF1, bf1, 0, hh, ROWS, DFF, D_MODEL, 1);
    gemm_on(s0, hh, wh + OF2, bf2, Ob, 0, ROWS, D_MODEL, DFF, 0);
    add_ln_kernel<<<ROWS, 256, 0, s0>>>(X2, Ob, g3, be3, out, 0);
}

// round 15
// speedup vs baseline: 1.1160x; 1.0030x over previous
#include <cuda_runtime.h>
#include <cuda_fp16.h>
#include <cstdint>
#include <math.h>

#define D_MODEL 1024
#define SEQ     2048
#define BATCH   2
#define NHEAD   16
#define DKH     64
#define DFF     4096
#define ROWS    (BATCH*SEQ)   // 4096
#define MEG     (1024*1024)

typedef __half fp16;

// ---------------- scratch (static __device__ arrays; no allocation) ----------------
__device__ float g_bufO[ROWS*D_MODEL];
__device__ float g_bufX1[ROWS*D_MODEL];
__device__ float g_bufX2[ROWS*D_MODEL];
__device__ float g_bias3[3*D_MODEL];
__device__ float g_bias2[2*D_MODEL];

__device__ fp16 g_xh[ROWS*D_MODEL];
__device__ fp16 g_eh[ROWS*D_MODEL];
__device__ fp16 g_wh[16*MEG];
__device__ fp16 g_qkv[ROWS*3*D_MODEL];     // packed Q|K|V (self)
__device__ fp16 g_q2[ROWS*D_MODEL];
__device__ fp16 g_kv2[ROWS*2*D_MODEL];     // packed K|V (cross)
__device__ fp16 g_abh[ROWS*D_MODEL];
__device__ fp16 g_acth[ROWS*D_MODEL];
__device__ fp16 g_hh[ROWS*DFF];

// ---------------- PTX helpers ---------------------------------------------------------
__device__ __forceinline__ uint32_t smem_u32(const void* p) {
    uint32_t a;
    asm("{ .reg .u64 t; cvta.to.shared.u64 t, %1; cvt.u32.u64 %0, t; }" : "=r"(a) : "l"(p));
    return a;
}
#define CP_ASYNC16(dst, src) \
    asm volatile("cp.async.cg.shared.global [%0], [%1], 16;" :: "r"(dst), "l"(src))
#define CP_COMMIT()  asm volatile("cp.async.commit_group;" ::: "memory")
#define CP_WAIT1()   asm volatile("cp.async.wait_group 1;" ::: "memory")
#define CP_WAIT0()   asm volatile("cp.async.wait_group 0;" ::: "memory")

#define LDM_X4(r0, r1, r2, r3, addr) \
    asm volatile("ldmatrix.sync.aligned.m8n8.x4.shared.b16 {%0,%1,%2,%3}, [%4];" \
        : "=r"(r0), "=r"(r1), "=r"(r2), "=r"(r3) : "r"(addr))
#define LDM_X4T(r0, r1, r2, r3, addr) \
    asm volatile("ldmatrix.sync.aligned.m8n8.x4.trans.shared.b16 {%0,%1,%2,%3}, [%4];" \
        : "=r"(r0), "=r"(r1), "=r"(r2), "=r"(r3) : "r"(addr))

#define MMA_F16(c, a, b0, b1) \
    asm volatile("mma.sync.aligned.m16n8k16.row.col.f32.f16.f16.f32 " \
        "{%0,%1,%2,%3}, {%4,%5,%6,%7}, {%8,%9}, {%0,%1,%2,%3};" \
        : "+f"((c)[0]), "+f"((c)[1]), "+f"((c)[2]), "+f"((c)[3]) \
        : "r"((a)[0]), "r"((a)[1]), "r"((a)[2]), "r"((a)[3]), "r"(b0), "r"(b1))

__device__ __forceinline__ uint32_t pack_h2(float lo, float hi) {
    __half2 t; t.x = __float2half_rn(lo); t.y = __float2half_rn(hi);
    return *(uint32_t*)&t;
}

// ---------------- tensor-core GEMM: C[M,N] = A B^T + bias ----------------------------
// 128x128 CTA tile, 8 warps (64x32), KC=64, 3-stage cp.async ring, one sync per chunk.
#define GKC      64
#define GLDS_EL  72
#define GLDS_B   (GLDS_EL*2)        // 144 B
#define GTILE_B  (128*GLDS_B)       // 18432 B
#define GBUF_B   (2*GTILE_B)        // 36864 B per stage
#define GSTAGES  3
#define GEMM_SMEM (GSTAGES*GBUF_B)  // 110592 B

__global__ __launch_bounds__(256)
void gemm_tc(const fp16* __restrict__ A, const fp16* __restrict__ B,
             const float* __restrict__ bias, float* __restrict__ C,
             fp16* __restrict__ Ch,
             int M, int N, int K, int relu, float oscale, int scaleN)
{
    extern __shared__ char smem[];
    const uint32_t sb = smem_u32(smem);
    const int tid  = threadIdx.x;
    const int wid  = tid >> 5, lane = tid & 31;
    const int rowBase = blockIdx.y * 128;
    const int colBase = blockIdx.x * 128;
    const int warpRow = (wid & 1) * 64;
    const int warpCol = (wid >> 1) * 32;

    const fp16* srcs[2]  = {A, B};
    const int   rbase[2] = {rowBase, colBase};
    const int nch = K / GKC;

    const int aRowL = (lane & 7) + ((lane >> 3) & 1) * 8;
    const int aColL = (lane >> 4) * 8;
    const int bRowL = (lane & 7) + (lane >> 4) * 8;
    const int bColL = ((lane >> 3) & 1) * 8;

    float acc[4][4][4];
#pragma unroll
    for (int mt = 0; mt < 4; mt++)
#pragma unroll
        for (int nt = 0; nt < 4; nt++)
#pragma unroll
            for (int r = 0; r < 4; r++) acc[mt][nt][r] = 0.f;

    auto issue_chunk = [&](int chunk, int stage) {
        const uint32_t dbase = sb + stage * GBUF_B;
        const int gk = chunk * GKC;
#pragma unroll
        for (int i = 0; i < 8; i++) {
            const int tile = i >> 2;
            const int within = (i & 3) * 256 + tid;
            const int r = within >> 3, seg = within & 7;
            const fp16* gp = srcs[tile] + (size_t)(rbase[tile] + r) * K + gk + seg * 8;
            CP_ASYNC16(dbase + tile * GTILE_B + r * GLDS_B + seg * 16, gp);
        }
        CP_COMMIT();
    };

    issue_chunk(0, 0);
    issue_chunk(1, 1);

    for (int kc = 0; kc < nch; kc++) {
        if (kc + 1 < nch) { CP_WAIT1(); } else { CP_WAIT0(); }
        __syncthreads();

        const uint32_t cb = sb + (kc % GSTAGES) * GBUF_B;
        const uint32_t As = cb, Bs = cb + GTILE_B;

#pragma unroll
        for (int ks = 0; ks < 4; ks++) {
            const int kcol = ks * 16;
            uint32_t af[4][4], bf[2][4];
#pragma unroll
            for (int mt = 0; mt < 4; mt++) {
                const uint32_t off = (uint32_t)(warpRow + mt * 16 + aRowL) * GLDS_B
                                   + (uint32_t)(kcol + aColL) * 2;
                LDM_X4(af[mt][0], af[mt][1], af[mt][2], af[mt][3], As + off);
            }
#pragma unroll
            for (int ntp = 0; ntp < 2; ntp++) {
                const uint32_t off = (uint32_t)(warpCol + ntp * 16 + bRowL) * GLDS_B
                                   + (uint32_t)(kcol + bColL) * 2;
                LDM_X4(bf[ntp][0], bf[ntp][1], bf[ntp][2], bf[ntp][3], Bs + off);
            }
#pragma unroll
            for (int mt = 0; mt < 4; mt++)
#pragma unroll
                for (int nt = 0; nt < 4; nt++) {
                    const int ntp = nt >> 1, q = (nt & 1) * 2;
                    MMA_F16(acc[mt][nt], af[mt], bf[ntp][q], bf[ntp][q + 1]);
                }
        }

        if (kc + 2 < nch) issue_chunk(kc + 2, (kc + 2) % GSTAGES);
    }

    const int lr = lane >> 2, lc = (lane & 3) * 2;
#pragma unroll
    for (int mt = 0; mt < 4; mt++) {
#pragma unroll
        for (int nt = 0; nt < 4; nt++) {
            const int col = colBase + warpCol + nt * 8 + lc;
            const float sc = (col < scaleN) ? oscale : 1.0f;
            const float b0 = __ldg(&bias[col]);
            const float b1 = __ldg(&bias[col + 1]);
#pragma unroll
            for (int h = 0; h < 2; h++) {
                const int row = rowBase + warpRow + mt * 16 + lr + h * 8;
                float v0 = acc[mt][nt][2 * h]     + b0;
                float v1 = acc[mt][nt][2 * h + 1] + b1;
                if (relu) { v0 = fmaxf(v0, 0.f); v1 = fmaxf(v1, 0.f); }
                v0 *= sc; v1 *= sc;
                const size_t off = (size_t)row * N + col;
                if (C) *(float2*)(C + off) = make_float2(v0, v1);
                if (Ch) {
                    __half2 hh; hh.x = __float2half_rn(v0); hh.y = __float2half_rn(v1);
                    *(__half2*)(Ch + off) = hh;
                }
            }
        }
    }
}

// ---------------- tensor-core flash attention -----------------------------------------
// CAUSAL: grid.x = SEQ/256; each CTA processes paired q-tiles {bx, 2*gridDim.x-1-bx}.
// non-causal: grid.x = SEQ/128, one q-tile per CTA.
#define FA_STR  72
#define FA_RB   (FA_STR*2)             // 144 B
#define FA_KVT  (64*FA_RB)             // 9216 B
#define FA_BUF  (2*FA_KVT)             // K,V
#define FA_SMEM (2*FA_BUF)             // 36864 B

template<bool CAUSAL>
__global__ __launch_bounds__(256)
void flash_tc(const fp16* __restrict__ Qh, const fp16* __restrict__ Kh,
              const fp16* __restrict__ Vh, fp16* __restrict__ Oh,
              int SK, int qstr, int kstr)
{
    extern __shared__ char smem[];
    const uint32_t sb = smem_u32(smem);
    const int tid = threadIdx.x;
    const int wid = tid >> 5, lane = tid & 31;
    const int b = blockIdx.z, h = blockIdx.y;

    const int nrep = CAUSAL ? 2 : 1;
    for (int rep = 0; rep < nrep; rep++) {
        const int qt = CAUSAL ? (rep == 0 ? (int)blockIdx.x
                                          : (int)(2 * gridDim.x - 1 - blockIdx.x))
                              : (int)blockIdx.x;
        const int qbase = qt * 128;

        const size_t qoff = ((size_t)b * SEQ + qbase) * qstr + h * DKH;
        const size_t koff = (size_t)b * SK * kstr + h * DKH;

        // stage Q, build fragments, release smem
        {
            const fp16* qp = Qh + qoff;
#pragma unroll
            for (int i = 0; i < 4; i++) {
                const int idx = i * 256 + tid;
                const int r = idx >> 3, seg = idx & 7;
                CP_ASYNC16(sb + r * FA_RB + seg * 16, qp + (size_t)r * qstr + seg * 8);
            }
            CP_COMMIT();
            CP_WAIT0();
            __syncthreads();
        }

        const int aRowL = (lane & 7) + ((lane >> 3) & 1) * 8;
        const int aColL = (lane >> 4) * 8;
        uint32_t qf[4][4];
#pragma unroll
        for (int ks = 0; ks < 4; ks++) {
            const uint32_t off = (uint32_t)(wid * 16 + aRowL) * FA_RB
                               + (uint32_t)(ks * 16 + aColL) * 2;
            LDM_X4(qf[ks][0], qf[ks][1], qf[ks][2], qf[ks][3], sb + off);
        }
        __syncthreads();

        float o[8][4];
#pragma unroll
        for (int dt = 0; dt < 8; dt++)
#pragma unroll
            for (int r = 0; r < 4; r++) o[dt][r] = 0.f;
        float m0 = -1e30f, m1 = -1e30f, l0 = 0.f, l1 = 0.f;

        const int r0g = qbase + wid * 16 + (lane >> 2);
        const int r1g = r0g + 8;
        const int nkt = CAUSAL ? (qt * 2 + 2) : (SK >> 6);

        // prologue: tile 0 -> buf 0
        {
#pragma unroll
            for (int i = 0; i < 2; i++) {
                const int idx = i * 256 + tid;
                const int r = idx >> 3, seg = idx & 7;
                const size_t g = koff + (size_t)r * kstr + seg * 8;
                CP_ASYNC16(sb + 0 * FA_KVT + r * FA_RB + seg * 16, Kh + g);
                CP_ASYNC16(sb + 1 * FA_KVT + r * FA_RB + seg * 16, Vh + g);
            }
            CP_COMMIT();
        }

        const int bRowL = (lane & 7) + (lane >> 4) * 8;
        const int bColL = ((lane >> 3) & 1) * 8;
        const int vRowL = lane & 15;
        const int vColL = (lane >> 4) * 8;

        for (int kt = 0; kt < nkt; kt++) {
            if (kt + 1 < nkt) {
                const uint32_t db = sb + ((kt + 1) & 1) * FA_BUF;
                const size_t kb = koff + (size_t)(kt + 1) * 64 * kstr;
#pragma unroll
                for (int i = 0; i < 2; i++) {
                    const int idx = i * 256 + tid;
                    const int r = idx >> 3, seg = idx & 7;
                    const size_t g = kb + (size_t)r * kstr + seg * 8;
                    CP_ASYNC16(db + 0 * FA_KVT + r * FA_RB + seg * 16, Kh + g);
                    CP_ASYNC16(db + 1 * FA_KVT + r * FA_RB + seg * 16, Vh + g);
                }
                CP_COMMIT();
                CP_WAIT1();
            } else {
                CP_WAIT0();
            }
            __syncthreads();

            const uint32_t cb = sb + (kt & 1) * FA_BUF;
            const uint32_t Khs = cb, Vhs = cb + FA_KVT;

            float s[8][4];
#pragma unroll
            for (int nt = 0; nt < 8; nt++)
#pragma unroll
                for (int r = 0; r < 4; r++) s[nt][r] = 0.f;

#pragma unroll
            for (int ks = 0; ks < 4; ks++) {
#pragma unroll
                for (int np = 0; np < 4; np++) {
                    uint32_t kf[4];
                    const uint32_t off = (uint32_t)(np * 16 + bRowL) * FA_RB
                                       + (uint32_t)(ks * 16 + bColL) * 2;
                    LDM_X4(kf[0], kf[1], kf[2], kf[3], Khs + off);
#pragma unroll
                    for (int hf = 0; hf < 2; hf++) {
                        const int nt = np * 2 + hf, q = hf * 2;
                        MMA_F16(s[nt], qf[ks], kf[q], kf[q + 1]);
                    }
                }
            }

            if (CAUSAL) {
                const int kb = kt * 64;
                if (kb + 63 > r0g) {
#pragma unroll
                    for (int nt = 0; nt < 8; nt++)
#pragma unroll
                        for (int c = 0; c < 2; c++) {
                            const int key = kb + nt * 8 + ((lane & 3) << 1) + c;
                            if (key > r0g) s[nt][c]     = -1e30f;
                            if (key > r1g) s[nt][2 + c] = -1e30f;
                        }
                }
            }

            float mx0 = -1e30f, mx1 = -1e30f;
#pragma unroll
            for (int nt = 0; nt < 8; nt++) {
                mx0 = fmaxf(mx0, fmaxf(s[nt][0], s[nt][1]));
                mx1 = fmaxf(mx1, fmaxf(s[nt][2], s[nt][3]));
            }
            mx0 = fmaxf(mx0, __shfl_xor_sync(0xffffffffu, mx0, 1, 4));
            mx0 = fmaxf(mx0, __shfl_xor_sync(0xffffffffu, mx0, 2, 4));
            mx1 = fmaxf(mx1, __shfl_xor_sync(0xffffffffu, mx1, 1, 4));
            mx1 = fmaxf(mx1, __shfl_xor_sync(0xffffffffu, mx1, 2, 4));
            const float mn0 = fmaxf(m0, mx0), mn1 = fmaxf(m1, mx1);
            const float c0 = exp2f(m0 - mn0), c1 = exp2f(m1 - mn1);
            float rs0 = 0.f, rs1 = 0.f;
#pragma unroll
            for (int nt = 0; nt < 8; nt++) {
                s[nt][0] = exp2f(s[nt][0] - mn0);
                s[nt][1] = exp2f(s[nt][1] - mn0);
                s[nt][2] = exp2f(s[nt][2] - mn1);
                s[nt][3] = exp2f(s[nt][3] - mn1);
                rs0 += s[nt][0] + s[nt][1];
                rs1 += s[nt][2] + s[nt][3];
            }
            rs0 += __shfl_xor_sync(0xffffffffu, rs0, 1, 4);
            rs0 += __shfl_xor_sync(0xffffffffu, rs0, 2, 4);
            rs1 += __shfl_xor_sync(0xffffffffu, rs1, 1, 4);
            rs1 += __shfl_xor_sync(0xffffffffu, rs1, 2, 4);
            l0 = l0 * c0 + rs0; l1 = l1 * c1 + rs1;
            m0 = mn0; m1 = mn1;
#pragma unroll
            for (int dt = 0; dt < 8; dt++) {
                o[dt][0] *= c0; o[dt][1] *= c0;
                o[dt][2] *= c1; o[dt][3] *= c1;
            }

#pragma unroll
            for (int ks = 0; ks < 4; ks++) {
                const int nt0 = 2 * ks, nt1 = 2 * ks + 1;
                uint32_t pf[4];
                pf[0] = pack_h2(s[nt0][0], s[nt0][1]);
                pf[1] = pack_h2(s[nt0][2], s[nt0][3]);
                pf[2] = pack_h2(s[nt1][0], s[nt1][1]);
                pf[3] = pack_h2(s[nt1][2], s[nt1][3]);
#pragma unroll
                for (int dp = 0; dp < 4; dp++) {
                    uint32_t vf[4];
                    const uint32_t off = (uint32_t)(ks * 16 + vRowL) * FA_RB
                                       + (uint32_t)(dp * 16 + vColL) * 2;
                    LDM_X4T(vf[0], vf[1], vf[2], vf[3], Vhs + off);
#pragma unroll
                    for (int hf = 0; hf < 2; hf++) {
                        const int dt = dp * 2 + hf, q = hf * 2;
                        MMA_F16(o[dt], pf, vf[q], vf[q + 1]);
                    }
                }
            }
            __syncthreads();
        }

        const float i0 = 1.f / l0, i1 = 1.f / l1;
        const int dcol = h * DKH + (lane & 3) * 2;
        const size_t ro0 = ((size_t)b * SEQ + r0g) * D_MODEL;
        const size_t ro1 = ((size_t)b * SEQ + r1g) * D_MODEL;
#pragma unroll
        for (int dt = 0; dt < 8; dt++) {
            const int dc = dcol + dt * 8;
            __half2 hh0; hh0.x = __float2half_rn(o[dt][0] * i0); hh0.y = __float2half_rn(o[dt][1] * i0);
            __half2 hh1; hh1.x = __float2half_rn(o[dt][2] * i1); hh1.y = __float2half_rn(o[dt][3] * i1);
            *(__half2*)(Oh + ro0 + dc) = hh0;
            *(__half2*)(Oh + ro1 + dc) = hh1;
        }
    }
}

// ---------------- fused residual-add + LayerNorm (+ fp16 out) ------------------------
__global__ __launch_bounds__(256)
void add_ln_kernel(const float* __restrict__ X, const float* __restrict__ R,
                   const float* __restrict__ gamma, const float* __restrict__ beta,
                   float* __restrict__ Y, fp16* __restrict__ Yh)
{
    const int row = blockIdx.x;
    const int t = threadIdx.x;
    const float4 xv = ((const float4*)(X + (size_t)row * D_MODEL))[t];
    const float4 rv = ((const float4*)(R + (size_t)row * D_MODEL))[t];
    float v0 = xv.x + rv.x, v1 = xv.y + rv.y, v2 = xv.z + rv.z, v3 = xv.w + rv.w;

    float s  = v0 + v1 + v2 + v3;
    float ss = v0 * v0 + v1 * v1 + v2 * v2 + v3 * v3;
#pragma unroll
    for (int o = 16; o > 0; o >>= 1) {
        s  += __shfl_xor_sync(0xffffffffu, s,  o);
        ss += __shfl_xor_sync(0xffffffffu, ss, o);
    }
    __shared__ float sbuf[8], ssbuf[8];
    int w = t >> 5, ln = t & 31;
    if (ln == 0) { sbuf[w] = s; ssbuf[w] = ss; }
    __syncthreads();
    s = 0.f; ss = 0.f;
#pragma unroll
    for (int i = 0; i < 8; i++) { s += sbuf[i]; ss += ssbuf[i]; }

    const float mu  = s * (1.f / 1024.f);
    const float var = ss * (1.f / 1024.f) - mu * mu;
    const float rs  = rsqrtf(var + 1e-5f);
    const float4 gv = ((const float4*)gamma)[t];
    const float4 bv = ((const float4*)beta)[t];
    float4 o;
    o.x = (v0 - mu) * rs * gv.x + bv.x;
    o.y = (v1 - mu) * rs * gv.y + bv.y;
    o.z = (v2 - mu) * rs * gv.z + bv.z;
    o.w = (v3 - mu) * rs * gv.w + bv.w;
    ((float4*)(Y + (size_t)row * D_MODEL))[t] = o;

    if (Yh) {
        size_t off = (size_t)row * D_MODEL + t * 4;
        __half2 hh0; hh0.x = __float2half_rn(o.x); hh0.y = __float2half_rn(o.y);
        __half2 hh1; hh1.x = __float2half_rn(o.z); hh1.y = __float2half_rn(o.w);
        *(__half2*)(Yh + off)     = hh0;
        *(__half2*)(Yh + off + 2) = hh1;
    }
}

// ---------------- fp32 -> fp16 converts -----------------------------------------------
__global__ __launch_bounds__(256)
void cvt_kernel(const float4* __restrict__ src, __half2* __restrict__ dst, int n4)
{
    int i = blockIdx.x * blockDim.x + threadIdx.x;
    if (i >= n4) return;
    float4 v = src[i];
    __half2 a; a.x = __float2half_rn(v.x); a.y = __float2half_rn(v.y);
    __half2 b; b.x = __float2half_rn(v.z); b.y = __float2half_rn(v.w);
    dst[2 * i] = a; dst[2 * i + 1] = b;
}

// converts 5 attention weight matrices (Wq1,Wk1,Wv1,Wo1,Wq2) into g_wh[0..5M).
// Launched with 5*MEG/4 threads (one per float4).
__global__ __launch_bounds__(256)
void cvt_w5_kernel(const float4* w0, const float4* w1, const float4* w2, const float4* w3,
                   const float4* w4, __half2* __restrict__ dst)
{
    const int i = blockIdx.x * blockDim.x + threadIdx.x;       // 0 .. 5*S-1 float4s
    const int S = MEG / 4;                                     // 262144 float4 per MEG
    const int slot = i >> 18;
    const float4* src; int off;
    switch (slot) {
        case 0: src = w0; off = i;         break;
        case 1: src = w1; off = i - S;     break;
        case 2: src = w2; off = i - 2*S;   break;
        case 3: src = w3; off = i - 3*S;   break;
        default: src = w4; off = i - 4*S;  break;
    }
    float4 v = src[off];
    __half2 a; a.x = __float2half_rn(v.x); a.y = __float2half_rn(v.y);
    __half2 b; b.x = __float2half_rn(v.z); b.y = __float2half_rn(v.w);
    dst[2 * i] = a; dst[2 * i + 1] = b;
}

// ---------------- orchestration -------------------------------------------------------
static inline void gemm_on(cudaStream_t st, const fp16* A, const fp16* B, const float* bias,
                           float* C, fp16* Ch, int M, int N, int K, int relu,
                           float oscale = 1.0f, int scaleN = 0)
{
    dim3 g(N / 128, M / 128);
    gemm_tc<<<g, 256, GEMM_SMEM, st>>>(A, B, bias, C, Ch, M, N, K, relu, oscale, scaleN);
}

static inline void cvt_on(cudaStream_t st, const float* src, fp16* dst, int n)
{
    int n4 = n / 4;
    cvt_kernel<<<(n4 + 255) / 256, 256, 0, st>>>((const float4*)src, (__half2*)dst, n4);
}

extern "C" void kernel_launch(void* const* d_in, const int* in_sizes, int n_in,
                              void* d_out, int out_size)
{
    const float* x   = (const float*)d_in[0];
    const float* enc = (const float*)d_in[1];
    const float* Wq1 = (const float*)d_in[4],  *bq1 = (const float*)d_in[5];
    const float* Wk1 = (const float*)d_in[6],  *bk1 = (const float*)d_in[7];
    const float* Wv1 = (const float*)d_in[8],  *bv1 = (const float*)d_in[9];
    const float* Wo1 = (const float*)d_in[10], *bo1 = (const float*)d_in[11];
    const float* Wq2 = (const float*)d_in[12], *bq2 = (const float*)d_in[13];
    const float* Wk2 = (const float*)d_in[14], *bk2 = (const float*)d_in[15];
    const float* Wv2 = (const float*)d_in[16], *bv2 = (const float*)d_in[17];
    const float* Wo2 = (const float*)d_in[18], *bo2 = (const float*)d_in[19];
    const float* Wf1 = (const float*)d_in[20], *bf1 = (const float*)d_in[21];
    const float* Wf2 = (const float*)d_in[22], *bf2 = (const float*)d_in[23];
    const float* g1  = (const float*)d_in[24], *be1 = (const float*)d_in[25];
    const float* g2  = (const float*)d_in[26], *be2 = (const float*)d_in[27];
    const float* g3  = (const float*)d_in[28], *be3 = (const float*)d_in[29];
    float* out = (float*)d_out;

    const float QSCALE = 0.125f * 1.4426950408889634f;
    const cudaStream_t s0 = 0;

    static cudaStream_t s2 = nullptr;
    static cudaEvent_t evFork = nullptr, evJoin = nullptr;
    if (!s2) {
        cudaStreamCreateWithFlags(&s2, cudaStreamNonBlocking);
        cudaEventCreateWithFlags(&evFork, cudaEventDisableTiming);
        cudaEventCreateWithFlags(&evJoin, cudaEventDisableTiming);
        cudaFuncSetAttribute(gemm_tc, cudaFuncAttributeMaxDynamicSharedMemorySize, GEMM_SMEM);
        cudaFuncSetAttribute(flash_tc<true>,  cudaFuncAttributeMaxDynamicSharedMemorySize, FA_SMEM);
        cudaFuncSetAttribute(flash_tc<false>, cudaFuncAttributeMaxDynamicSharedMemorySize, FA_SMEM);
    }

    float *Ob, *X1, *X2, *bias3, *bias2;
    cudaGetSymbolAddress((void**)&Ob, g_bufO);
    cudaGetSymbolAddress((void**)&X1, g_bufX1);
    cudaGetSymbolAddress((void**)&X2, g_bufX2);
    cudaGetSymbolAddress((void**)&bias3, g_bias3);
    cudaGetSymbolAddress((void**)&bias2, g_bias2);
    fp16 *xh, *eh, *wh, *qkv, *q2, *kv2, *abh, *acth, *hh;
    cudaGetSymbolAddress((void**)&xh,   g_xh);
    cudaGetSymbolAddress((void**)&eh,   g_eh);
    cudaGetSymbolAddress((void**)&wh,   g_wh);
    cudaGetSymbolAddress((void**)&qkv,  g_qkv);
    cudaGetSymbolAddress((void**)&q2,   g_q2);
    cudaGetSymbolAddress((void**)&kv2,  g_kv2);
    cudaGetSymbolAddress((void**)&abh,  g_abh);
    cudaGetSymbolAddress((void**)&acth, g_acth);
    cudaGetSymbolAddress((void**)&hh,   g_hh);

    // packed weight slots (elements): QKV1 at 0, O1 at 3M, Q2 at 4M, KV2 at 5M, O2 at 7M
    const size_t OQKV1 = 0, OO1 = 3 * MEG, OQ2 = 4 * MEG, OKV2 = 5 * MEG, OO2 = 7 * MEG;
    const size_t OF1 = 8 * MEG, OF2 = 12 * MEG;

    // ---- front matter on main stream: only weights s0 itself needs pre-join ----
    cvt_w5_kernel<<<(5 * MEG / 4) / 256, 256, 0, s0>>>(
        (const float4*)Wq1, (const float4*)Wk1, (const float4*)Wv1, (const float4*)Wo1,
        (const float4*)Wq2, (__half2*)wh);
    cvt_on(s0, x, xh, ROWS * D_MODEL);
    cudaMemcpyAsync(bias3,             bq1, D_MODEL * 4, cudaMemcpyDeviceToDevice, s0);
    cudaMemcpyAsync(bias3 + D_MODEL,   bk1, D_MODEL * 4, cudaMemcpyDeviceToDevice, s0);
    cudaMemcpyAsync(bias3 + 2*D_MODEL, bv1, D_MODEL * 4, cudaMemcpyDeviceToDevice, s0);
    cudaMemcpyAsync(bias2,             bk2, D_MODEL * 4, cudaMemcpyDeviceToDevice, s0);
    cudaMemcpyAsync(bias2 + D_MODEL,   bv2, D_MODEL * 4, cudaMemcpyDeviceToDevice, s0);

    // ---- fork: Wk2/Wv2/Wo2 + FFN weight converts + cross-attn KV path on s2 ----
    cudaEventRecord(evFork, s0);
    cudaStreamWaitEvent(s2, evFork, 0);
    cvt_on(s2, Wk2, wh + OKV2, MEG);
    cvt_on(s2, Wv2, wh + OKV2 + MEG, MEG);
    cvt_on(s2, Wo2, wh + OO2, MEG);
    cvt_on(s2, Wf1, wh + OF1, 4 * MEG);
    cvt_on(s2, Wf2, wh + OF2, 4 * MEG);
    cvt_on(s2, enc, eh, ROWS * D_MODEL);
    gemm_on(s2, eh, wh + OKV2, bias2, 0, kv2, ROWS, 2 * D_MODEL, D_MODEL, 0);
    cudaEventRecord(evJoin, s2);

    dim3 gf1(SEQ / 256, NHEAD, BATCH);   // causal: paired q-tiles
    dim3 gf2(SEQ / 128, NHEAD, BATCH);   // cross: one q-tile per CTA

    // ---- self-attention (causal): fused QKV projection, N=3072 ----
    gemm_on(s0, xh, wh + OQKV1, bias3, 0, qkv, ROWS, 3 * D_MODEL, D_MODEL, 0, QSCALE, D_MODEL);
    flash_tc<true><<<gf1, 256, FA_SMEM, s0>>>(qkv, qkv + D_MODEL, qkv + 2 * D_MODEL, abh,
                                              SEQ, 3 * D_MODEL, 3 * D_MODEL);
    gemm_on(s0, abh, wh + OO1, bo1, Ob, 0, ROWS, D_MODEL, D_MODEL, 0);
    add_ln_kernel<<<ROWS, 256, 0, s0>>>(x, Ob, g1, be1, X1, acth);

    // ---- cross-attention: Q projection on main, KV already in flight on s2 ----
    gemm_on(s0, acth, wh + OQ2, bq2, 0, q2, ROWS, D_MODEL, D_MODEL, 0, QSCALE, D_MODEL);
    cudaStreamWaitEvent(s0, evJoin, 0);
    flash_tc<false><<<gf2, 256, FA_SMEM, s0>>>(q2, kv2, kv2 + D_MODEL, abh,
                                               SEQ, D_MODEL, 2 * D_MODEL);
    gemm_on(s0, abh, wh + OO2, bo2, Ob, 0, ROWS, D_MODEL, D_MODEL, 0);
    add_ln_kernel<<<ROWS, 256, 0, s0>>>(X1, Ob, g2, be2, X2, acth);

    // ---- FFN ----
    gemm_on(s0, acth, wh + OF1, bf1, 0, hh, ROWS, DFF, D_MODEL, 1);
    gemm_on(s0, hh, wh + OF2, bf2, Ob, 0, ROWS, D_MODEL, DFF, 0);
    add_ln_kernel<<<ROWS, 256, 0, s0>>>(X2, Ob, g3, be3, out, 0);
}